// round 4
// baseline (speedup 1.0000x reference)
#include <cuda_runtime.h>
#include <cuda_bf16.h>
#include <cstdint>
#include <cstddef>

// ---------------------------------------------------------------------------
// Problem constants
// ---------------------------------------------------------------------------
namespace cfg {
constexpr int B   = 4;
constexpr int Hn  = 160, Wn = 288;      // input H, W
constexpr int HOo = 80,  WOo = 144;     // output H, W (stride 2)
constexpr int HW  = HOo * WOo;          // 11520
constexpr int HWin = Hn * Wn;           // 46080
constexpr int Dd  = 24;                 // disparity levels
constexpr int G_CI = 96, G_CO = 192;
// mma conv tiling
constexpr int NCHUNK = 27;              // 27 chunks of 32 k (tap-major)
constexpr int MT = 128;                 // pixels per CTA
}

// Scratch (static device globals — no allocation allowed)
__device__ float d_y1 [(size_t)cfg::B * cfg::G_CO * cfg::HW];   // 35.4 MB
__device__ float d_g8x[(size_t)cfg::B * cfg::G_CI * cfg::HW];   // 17.7 MB
__device__ float d_y2 [(size_t)cfg::B * 24 * cfg::HW];          //  4.4 MB
__device__ float d_c8x[(size_t)cfg::B * 12 * cfg::HW];          //  2.2 MB
// Pre-split bf16 weights: [chunk 27][nhalf 2] blobs of 15360B
//   blob = [hi: 96 rows x 40 bf16][lo: 96 rows x 40 bf16] (rows padded to 80B)
__device__ uint4 d_wB[(size_t)cfg::NCHUNK * 2 * 960];

// ---------------------------------------------------------------------------
// PTX helpers (sm_80-compatible only: ldmatrix / mma.sync / cp.async)
// ---------------------------------------------------------------------------
__device__ __forceinline__ uint32_t smem_u32(const void* p) {
    uint32_t a;
    asm("{ .reg .u64 t; cvta.to.shared.u64 t, %1; cvt.u32.u64 %0, t; }" : "=r"(a) : "l"(p));
    return a;
}
__device__ __forceinline__ void ldsm4(uint32_t* r, uint32_t addr) {
    asm volatile("ldmatrix.sync.aligned.m8n8.x4.shared.b16 {%0,%1,%2,%3}, [%4];"
        : "=r"(r[0]), "=r"(r[1]), "=r"(r[2]), "=r"(r[3]) : "r"(addr));
}
__device__ __forceinline__ void mma_bf16(float* c, const uint32_t* a, const uint32_t* b) {
    asm volatile(
        "mma.sync.aligned.m16n8k16.row.col.f32.bf16.bf16.f32 "
        "{%0,%1,%2,%3}, {%4,%5,%6,%7}, {%8,%9}, {%0,%1,%2,%3};"
        : "+f"(c[0]), "+f"(c[1]), "+f"(c[2]), "+f"(c[3])
        : "r"(a[0]), "r"(a[1]), "r"(a[2]), "r"(a[3]), "r"(b[0]), "r"(b[1]));
}
#define CP_ASYNC16(dst, src) \
    asm volatile("cp.async.cg.shared.global [%0], [%1], 16;" :: "r"(dst), "l"(src) : "memory")
#define CP_COMMIT()  asm volatile("cp.async.commit_group;" ::: "memory")
#define CP_WAIT0()   asm volatile("cp.async.wait_group 0;" ::: "memory")

// ---------------------------------------------------------------------------
// Kernel 0: weight prep. k order: chunk = tap*3 + ci/32 ; within chunk k=ci%32.
// Splits w into bf16 hi/lo, pads rows to 40 bf16 (80B).
// ---------------------------------------------------------------------------
__global__ void wprep_kernel(const float* __restrict__ w) {
    using namespace cfg;
    int idx = blockIdx.x * blockDim.x + threadIdx.x;
    if (idx >= NCHUNK * 192 * 32) return;
    int k = idx & 31, co = (idx >> 5) % 192, c = idx / (32 * 192);
    int tap = c / 3, ci = (c % 3) * 32 + k;
    float v = w[(size_t)(co * G_CI + ci) * 9 + tap];
    __nv_bfloat16 hi = __float2bfloat16_rn(v);
    __nv_bfloat16 lo = __float2bfloat16_rn(v - __bfloat162float(hi));
    __nv_bfloat16* blob = (__nv_bfloat16*)d_wB + (size_t)(c * 2 + co / 96) * 7680;
    int col = co % 96;
    blob[col * 40 + k]        = hi;
    blob[3840 + col * 40 + k] = lo;
}

// ---------------------------------------------------------------------------
// Kernel 1: conv3x3 s2 p1 (96->192) + BN + leakyReLU, as implicit GEMM with
// mma.sync bf16 hi/lo compensation (3-product split, fp32 accumulate).
// CTA: 128 px x 96 co, 8 warps (4M x 2N), warp tile 32x48.
// smem (dynamic): 2 x [Ahi 10240 | Alo 10240 | Bhi 7680 | Blo 7680] + BN 768
// Epilogue reuses buffer 0 as a [96 co][128 px] fp32 transpose pad for
// coalesced float4 stores (BN fused in the read-out pass).
// ---------------------------------------------------------------------------
static constexpr int BUF_STRIDE = 35840;
static constexpr int SM_BN      = 2 * BUF_STRIDE;         // 71680
static constexpr int SM_CONV    = SM_BN + 768;            // 72448

__global__ void __launch_bounds__(256, 2)
conv_gwc_mma(const float* __restrict__ x,
             const float* __restrict__ bng, const float* __restrict__ bnb,
             const float* __restrict__ bnm, const float* __restrict__ bnv,
             float* __restrict__ y)
{
    using namespace cfg;
    extern __shared__ char smem[];
    const uint32_t sb = smem_u32(smem);
    const int t = threadIdx.x, lane = t & 31, wid = t >> 5;
    const int wm = wid & 3, wn = wid >> 2;

    float* sc_s = (float*)(smem + SM_BN);
    float* bi_s = (float*)(smem + SM_BN + 384);
    if (t < 96) {
        const int co = blockIdx.y * 96 + t;
        const float sc = bng[co] * rsqrtf(bnv[co] + 1e-5f);
        sc_s[t] = sc;
        bi_s[t] = bnb[co] - bnm[co] * sc;
    }

    // pixel owned for A staging
    const int pl = t & 127, khalf = t >> 7;
    const int p  = blockIdx.x * MT + pl;
    const int b  = p / HW;
    const int q  = p - b * HW;
    const int ho = q / WOo, wo = q - ho * WOo;
    const float* xb = x + (size_t)b * G_CI * HWin;

    // ldmatrix per-lane offset pieces
    const uint32_t a_off = (uint32_t)((lane & 7) + ((lane >> 3) & 1) * 8) * 80
                         + ((lane >> 4) << 4);
    const uint32_t b_off = (uint32_t)(((lane >> 4) * 8) + (lane & 7)) * 80
                         + (((lane >> 3) & 1) << 4);

    float acc[2][6][4];
    #pragma unroll
    for (int i = 0; i < 2; i++)
        #pragma unroll
        for (int j = 0; j < 6; j++)
            #pragma unroll
            for (int r = 0; r < 4; r++) acc[i][j][r] = 0.f;

    auto ldgA = [&](int c, float* v) {
        const int tap = c / 3, dy = tap / 3, dx = tap - dy * 3;
        const int ci0 = (c - tap * 3) * 32 + khalf * 16;
        const int h2 = 2 * ho - 1 + dy, w2 = 2 * wo - 1 + dx;
        const bool vr = ((unsigned)h2 < (unsigned)Hn) && ((unsigned)w2 < (unsigned)Wn);
        const float* xp = xb + (size_t)h2 * Wn + w2 + (size_t)ci0 * HWin;
        #pragma unroll
        for (int i = 0; i < 16; i++) v[i] = vr ? xp[(size_t)i * HWin] : 0.f;
    };
    auto stsA = [&](uint32_t bufb, const float* v) {
        uint32_t hp[8], lp[8];
        #pragma unroll
        for (int i = 0; i < 8; i++) {
            __nv_bfloat16 h0 = __float2bfloat16_rn(v[2*i]);
            __nv_bfloat16 h1 = __float2bfloat16_rn(v[2*i+1]);
            __nv_bfloat16 l0 = __float2bfloat16_rn(v[2*i]   - __bfloat162float(h0));
            __nv_bfloat16 l1 = __float2bfloat16_rn(v[2*i+1] - __bfloat162float(h1));
            hp[i] = (uint32_t)__bfloat16_as_ushort(h0) | ((uint32_t)__bfloat16_as_ushort(h1) << 16);
            lp[i] = (uint32_t)__bfloat16_as_ushort(l0) | ((uint32_t)__bfloat16_as_ushort(l1) << 16);
        }
        const uint32_t off = (uint32_t)pl * 80 + khalf * 32;
        *(uint4*)(smem + bufb + off)           = make_uint4(hp[0], hp[1], hp[2], hp[3]);
        *(uint4*)(smem + bufb + off + 16)      = make_uint4(hp[4], hp[5], hp[6], hp[7]);
        *(uint4*)(smem + bufb + 10240 + off)      = make_uint4(lp[0], lp[1], lp[2], lp[3]);
        *(uint4*)(smem + bufb + 10240 + off + 16) = make_uint4(lp[4], lp[5], lp[6], lp[7]);
    };
    auto cpB = [&](int c, uint32_t bufb) {
        const char* src = (const char*)d_wB + (size_t)(c * 2 + blockIdx.y) * 15360;
        const uint32_t dst = sb + bufb + 20480;
        #pragma unroll
        for (int j = t; j < 960; j += 256)
            CP_ASYNC16(dst + j * 16, src + (size_t)j * 16);
        CP_COMMIT();
    };

    // prologue: stage chunk 0 into buf 0
    {
        cpB(0, 0);
        float v0[16];
        ldgA(0, v0);
        stsA(0, v0);
        CP_WAIT0();
    }
    __syncthreads();

    float vnext[16];
    for (int c = 0; c < NCHUNK; c++) {
        const uint32_t bufb  = (uint32_t)(c & 1) * BUF_STRIDE;
        const uint32_t nbufb = (uint32_t)((c + 1) & 1) * BUF_STRIDE;
        const bool more = (c + 1 < NCHUNK);
        if (more) { cpB(c + 1, nbufb); ldgA(c + 1, vnext); }

        // ---- MMA on buf[c&1] ----
        const uint32_t Ah = sb + bufb, Al = Ah + 10240;
        const uint32_t Bh = sb + bufb + 20480, Bl = Bh + 7680;
        #pragma unroll
        for (int ks = 0; ks < 2; ks++) {
            uint32_t ah[2][4], al[2][4], bb[3][4];
            #pragma unroll
            for (int ma = 0; ma < 2; ma++) {
                const uint32_t ro = (uint32_t)(wm * 32 + ma * 16) * 80 + ks * 32 + a_off;
                ldsm4(ah[ma], Ah + ro);
                ldsm4(al[ma], Al + ro);
            }
            #pragma unroll
            for (int n2 = 0; n2 < 3; n2++) {
                const uint32_t ro = (uint32_t)(wn * 48 + n2 * 16) * 80 + ks * 32 + b_off;
                ldsm4(bb[n2], Bh + ro);
            }
            #pragma unroll
            for (int ma = 0; ma < 2; ma++)
                #pragma unroll
                for (int n2 = 0; n2 < 3; n2++) {
                    mma_bf16(acc[ma][2*n2],   ah[ma], bb[n2]);
                    mma_bf16(acc[ma][2*n2+1], ah[ma], bb[n2] + 2);
                    mma_bf16(acc[ma][2*n2],   al[ma], bb[n2]);
                    mma_bf16(acc[ma][2*n2+1], al[ma], bb[n2] + 2);
                }
            #pragma unroll
            for (int n2 = 0; n2 < 3; n2++) {
                const uint32_t ro = (uint32_t)(wn * 48 + n2 * 16) * 80 + ks * 32 + b_off;
                ldsm4(bb[n2], Bl + ro);
            }
            #pragma unroll
            for (int ma = 0; ma < 2; ma++)
                #pragma unroll
                for (int n2 = 0; n2 < 3; n2++) {
                    mma_bf16(acc[ma][2*n2],   ah[ma], bb[n2]);
                    mma_bf16(acc[ma][2*n2+1], ah[ma], bb[n2] + 2);
                }
        }

        if (more) { stsA(nbufb, vnext); CP_WAIT0(); }
        __syncthreads();
    }

    // ---- epilogue: smem transpose -> BN + leaky relu -> coalesced float4 ----
    {
        float* ys = (float*)smem;               // [96 co][128 px]
        const int t4 = lane >> 2, tp = (lane & 3) * 2;
        #pragma unroll
        for (int ma = 0; ma < 2; ma++) {
            const int r = wm * 32 + ma * 16 + t4;
            #pragma unroll
            for (int na = 0; na < 6; na++) {
                const int lc = wn * 48 + na * 8 + tp;
                ys[(size_t)lc * 128 + r]            = acc[ma][na][0];
                ys[(size_t)(lc + 1) * 128 + r]      = acc[ma][na][1];
                ys[(size_t)lc * 128 + r + 8]        = acc[ma][na][2];
                ys[(size_t)(lc + 1) * 128 + r + 8]  = acc[ma][na][3];
            }
        }
        __syncthreads();
        const int bt = (blockIdx.x * MT) / HW;          // tile never straddles b
        const int q0 = blockIdx.x * MT - bt * HW;
        float* yb = y + ((size_t)bt * G_CO + blockIdx.y * 96) * HW + q0;
        #pragma unroll
        for (int i = 0; i < 12; i++) {
            const int idx = t + i * 256;        // co*32 + p4
            const int co = idx >> 5, p4 = idx & 31;
            const float s = sc_s[co], bi = bi_s[co];
            float4 v = *(float4*)&ys[(size_t)co * 128 + p4 * 4];
            v.x = fmaf(v.x, s, bi); v.x = (v.x >= 0.f) ? v.x : 0.1f * v.x;
            v.y = fmaf(v.y, s, bi); v.y = (v.y >= 0.f) ? v.y : 0.1f * v.y;
            v.z = fmaf(v.z, s, bi); v.z = (v.z >= 0.f) ? v.z : 0.1f * v.z;
            v.w = fmaf(v.w, s, bi); v.w = (v.w >= 0.f) ? v.w : 0.1f * v.w;
            *(float4*)(yb + (size_t)co * HW + p4 * 4) = v;
        }
    }
}

// ---------------------------------------------------------------------------
// Direct fp32 conv (tiny cat path: 12->24)
// ---------------------------------------------------------------------------
template<int CI, int CO_T, int HO_T, int WO_T>
__global__ void __launch_bounds__(WO_T * (CO_T / 4))
conv3x3s2_bn_lrelu(const float* __restrict__ x, const float* __restrict__ wgt,
                   const float* __restrict__ bng, const float* __restrict__ bnb,
                   const float* __restrict__ bnm, const float* __restrict__ bnv,
                   float* __restrict__ y, int CO, int tiles_x)
{
    using namespace cfg;
    constexpr int NTh  = WO_T * (CO_T / 4);
    constexpr int IN_H = 2 * HO_T + 1;
    constexpr int IN_W = 2 * WO_T + 1;

    __shared__ float xe[IN_H][WO_T + 2];
    __shared__ float xo[IN_H][WO_T + 1];
    __shared__ float ws[CO_T * 9];

    const int tx  = blockIdx.x % tiles_x;
    const int ty  = blockIdx.x / tiles_x;
    const int wo0 = tx * WO_T, ho0 = ty * HO_T;
    const int co0 = blockIdx.y * CO_T;
    const int b   = blockIdx.z;
    const int tid = threadIdx.x;
    const int px  = tid % WO_T;
    const int cg  = tid / WO_T;

    float acc[4][HO_T];
    #pragma unroll
    for (int j = 0; j < 4; j++)
        #pragma unroll
        for (int r = 0; r < HO_T; r++) acc[j][r] = 0.f;

    const float* xb = x + (size_t)b * CI * Hn * Wn;
    const int h_base = 2 * ho0 - 1, w_base = 2 * wo0 - 1;

    for (int ci = 0; ci < CI; ci++) {
        const float* xc = xb + (size_t)ci * Hn * Wn;
        for (int i = tid; i < IN_H * IN_W; i += NTh) {
            int r = i / IN_W, c = i - r * IN_W;
            int hh = h_base + r, ww = w_base + c;
            float v = 0.f;
            if ((unsigned)hh < (unsigned)Hn && (unsigned)ww < (unsigned)Wn)
                v = xc[hh * Wn + ww];
            if (c & 1) xo[r][c >> 1] = v; else xe[r][c >> 1] = v;
        }
        for (int i = tid; i < CO_T * 9; i += NTh)
            ws[i] = wgt[((size_t)(co0 + i / 9) * CI + ci) * 9 + (i % 9)];
        __syncthreads();

        float wr[4][9];
        #pragma unroll
        for (int j = 0; j < 4; j++)
            #pragma unroll
            for (int tt = 0; tt < 9; tt++)
                wr[j][tt] = ws[(cg * 4 + j) * 9 + tt];

        #pragma unroll
        for (int ir = 0; ir < IN_H; ir++) {
            const float x0 = xe[ir][px];
            const float x1 = xo[ir][px];
            const float x2 = xe[ir][px + 1];
            #pragma unroll
            for (int dy = 0; dy < 3; dy++) {
                const int rn = ir - dy;
                if ((rn & 1) == 0 && rn >= 0 && rn < 2 * HO_T) {
                    const int r = rn >> 1;
                    #pragma unroll
                    for (int j = 0; j < 4; j++) {
                        acc[j][r] = fmaf(x0, wr[j][dy * 3 + 0], acc[j][r]);
                        acc[j][r] = fmaf(x1, wr[j][dy * 3 + 1], acc[j][r]);
                        acc[j][r] = fmaf(x2, wr[j][dy * 3 + 2], acc[j][r]);
                    }
                }
            }
        }
        __syncthreads();
    }

    #pragma unroll
    for (int j = 0; j < 4; j++) {
        const int co = co0 + cg * 4 + j;
        const float sc = bng[co] * rsqrtf(bnv[co] + 1e-5f);
        const float bi = bnb[co] - bnm[co] * sc;
        #pragma unroll
        for (int r = 0; r < HO_T; r++) {
            float v = fmaf(acc[j][r], sc, bi);
            v = (v >= 0.f) ? v : 0.1f * v;
            y[((size_t)(b * CO + co) * HOo + (ho0 + r)) * WOo + wo0 + px] = v;
        }
    }
}

// ---------------------------------------------------------------------------
// Fused 1x1 conv -> softmax(9) -> unfold-weighted sum, smem-staged y tile.
// Block: 48 px x 1 ho row; G*12 threads (thread = (group g, quad q)).
// The y tile is loaded once into smem, killing the Gx redundant L1 reads.
// ---------------------------------------------------------------------------
template<int CI_X, int CIY, int G, int CPG>
__global__ void __launch_bounds__(G * 12)
mask_softmax_unfold(const float* __restrict__ y, const float* __restrict__ w2,
                    const float* __restrict__ x, float* __restrict__ out)
{
    using namespace cfg;
    constexpr int NT = G * 12;
    __shared__ float yt[CIY][48];

    const int wo0 = blockIdx.x * 48;
    const int ho  = blockIdx.y;
    const int b   = blockIdx.z;
    const int tid = threadIdx.x;
    const int q   = tid % 12;
    const int g   = tid / 12;
    const int px0 = wo0 + q * 4;

    // stage the [CIY][48] y tile (each row: 12 float4 loads, coalesced)
    const float* yb = y + (size_t)b * CIY * HW + (size_t)ho * WOo + wo0;
    for (int i = tid; i < CIY * 12; i += NT) {
        const int ch = i / 12, j = i % 12;
        *(float4*)&yt[ch][j * 4] = *(const float4*)(yb + (size_t)ch * HW + j * 4);
    }
    __syncthreads();

    float lg[9][4];
    #pragma unroll
    for (int j = 0; j < 9; j++)
        #pragma unroll
        for (int p = 0; p < 4; p++) lg[j][p] = 0.f;

    const float* wg = w2 + (size_t)g * 9 * CIY;

    for (int c4 = 0; c4 < CIY; c4 += 4) {
        float4 yv0 = *(const float4*)&yt[c4 + 0][q * 4];
        float4 yv1 = *(const float4*)&yt[c4 + 1][q * 4];
        float4 yv2 = *(const float4*)&yt[c4 + 2][q * 4];
        float4 yv3 = *(const float4*)&yt[c4 + 3][q * 4];
        #pragma unroll
        for (int j = 0; j < 9; j++) {
            float4 wv = *(const float4*)(wg + j * CIY + c4);
            lg[j][0] += wv.x * yv0.x + wv.y * yv1.x + wv.z * yv2.x + wv.w * yv3.x;
            lg[j][1] += wv.x * yv0.y + wv.y * yv1.y + wv.z * yv2.y + wv.w * yv3.y;
            lg[j][2] += wv.x * yv0.z + wv.y * yv1.z + wv.z * yv2.z + wv.w * yv3.z;
            lg[j][3] += wv.x * yv0.w + wv.y * yv1.w + wv.z * yv2.w + wv.w * yv3.w;
        }
    }

    #pragma unroll
    for (int p = 0; p < 4; p++) {
        float mx = lg[0][p];
        #pragma unroll
        for (int j = 1; j < 9; j++) mx = fmaxf(mx, lg[j][p]);
        float s = 0.f;
        #pragma unroll
        for (int j = 0; j < 9; j++) { float e = expf(lg[j][p] - mx); lg[j][p] = e; s += e; }
        const float inv = 1.f / s;
        #pragma unroll
        for (int j = 0; j < 9; j++) lg[j][p] *= inv;
    }

    #pragma unroll
    for (int io = 0; io < CPG; io++) {
        const int ch = io * G + g;
        const float* xc = x + (size_t)(b * CI_X + ch) * Hn * Wn;
        float o[4] = {0.f, 0.f, 0.f, 0.f};
        #pragma unroll
        for (int dy = 0; dy < 3; dy++) {
            const int h2 = 2 * ho + dy - 1;
            if ((unsigned)h2 < (unsigned)Hn) {
                const float* xr = xc + (size_t)h2 * Wn;
                const int wb = 2 * px0 - 1;
                float xv[9];
                #pragma unroll
                for (int k = 0; k < 9; k++) {
                    const int wi = wb + k;
                    xv[k] = ((unsigned)wi < (unsigned)Wn) ? xr[wi] : 0.f;
                }
                #pragma unroll
                for (int p = 0; p < 4; p++)
                    #pragma unroll
                    for (int dx = 0; dx < 3; dx++)
                        o[p] = fmaf(lg[dy * 3 + dx][p], xv[2 * p + dx], o[p]);
            }
        }
        *(float4*)(out + ((size_t)(b * CI_X + ch) * HOo + ho) * WOo + px0) =
            make_float4(o[0], o[1], o[2], o[3]);
    }
}

// ---------------------------------------------------------------------------
// Cost volumes
// ---------------------------------------------------------------------------
__global__ void __launch_bounds__(288)
gwc_volume_kernel(const float* __restrict__ g8x, float* __restrict__ out)
{
    using namespace cfg;
    __shared__ float rs[2][12][WOo];
    const int h  = blockIdx.x * 2 + threadIdx.y;
    const int g  = blockIdx.y;
    const int b  = blockIdx.z;
    const int w  = threadIdx.x;
    const int hy = threadIdx.y;

    const float* rbase = g8x + ((size_t)((b + 2) * G_CI + g * 12) * HOo + h) * WOo;
    #pragma unroll
    for (int c = 0; c < 12; c++)
        rs[hy][c][w] = rbase[(size_t)c * HW + w];
    __syncthreads();

    const float* lbase = g8x + ((size_t)(b * G_CI + g * 12) * HOo + h) * WOo + w;
    float lr[12];
    #pragma unroll
    for (int c = 0; c < 12; c++) lr[c] = lbase[(size_t)c * HW];

    for (int d = 0; d < Dd; d++) {
        float s = 0.f;
        if (w >= d) {
            #pragma unroll
            for (int c = 0; c < 12; c++) s = fmaf(lr[c], rs[hy][c][w - d], s);
            s *= (1.f / 12.f);
        }
        out[(((size_t)(b * 32 + g) * Dd + d) * HOo + h) * WOo + w] = s;
    }
}

__global__ void cat_volume_kernel(const float* __restrict__ c8x, float* __restrict__ out)
{
    using namespace cfg;
    const int idx = blockIdx.x * blockDim.x + threadIdx.x;
    constexpr int TOT = 2 * 24 * Dd * HW;
    if (idx >= TOT) return;
    int t = idx;
    const int w = t % WOo;  t /= WOo;
    const int h = t % HOo;  t /= HOo;
    const int d = t % Dd;   t /= Dd;
    const int cc = t % 24;
    const int b  = t / 24;

    float v = 0.f;
    if (w >= d) {
        if (cc < 12)
            v = c8x[((size_t)(b * 12 + cc) * HOo + h) * WOo + w];
        else
            v = c8x[((size_t)((b + 2) * 12 + (cc - 12)) * HOo + h) * WOo + (w - d)];
    }
    out[(((size_t)(b * 32 + 8 + cc) * Dd + d) * HOo + h) * WOo + w] = v;
}

// ---------------------------------------------------------------------------
// Launch
// ---------------------------------------------------------------------------
extern "C" void kernel_launch(void* const* d_in, const int* in_sizes, int n_in,
                              void* d_out, int out_size)
{
    const float* gx  = (const float*)d_in[0];
    const float* cx  = (const float*)d_in[1];
    const float* gw1 = (const float*)d_in[2];
    const float* gbg = (const float*)d_in[3];
    const float* gbb = (const float*)d_in[4];
    const float* gbm = (const float*)d_in[5];
    const float* gbv = (const float*)d_in[6];
    const float* gw2 = (const float*)d_in[7];
    const float* cw1 = (const float*)d_in[8];
    const float* cbg = (const float*)d_in[9];
    const float* cbb = (const float*)d_in[10];
    const float* cbm = (const float*)d_in[11];
    const float* cbv = (const float*)d_in[12];
    const float* cw2 = (const float*)d_in[13];
    float* out = (float*)d_out;

    float *y1, *g8x, *y2, *c8x;
    cudaGetSymbolAddress((void**)&y1,  d_y1);
    cudaGetSymbolAddress((void**)&g8x, d_g8x);
    cudaGetSymbolAddress((void**)&y2,  d_y2);
    cudaGetSymbolAddress((void**)&c8x, d_c8x);

    cudaFuncSetAttribute(conv_gwc_mma, cudaFuncAttributeMaxDynamicSharedMemorySize, SM_CONV);

    wprep_kernel<<<(cfg::NCHUNK * 192 * 32 + 255) / 256, 256>>>(gw1);
    conv_gwc_mma<<<dim3(360, 2), 256, SM_CONV>>>(gx, gbg, gbb, gbm, gbv, y1);

    conv3x3s2_bn_lrelu<12, 24, 8, 48><<<dim3(30, 1, 4), 288>>>(
        cx, cw1, cbg, cbb, cbm, cbv, y2, 24, 3);

    mask_softmax_unfold<96, 192, 16, 6><<<dim3(3, 80, 4), 192>>>(y1, gw2, gx, g8x);
    mask_softmax_unfold<12, 24, 12, 1><<<dim3(3, 80, 4), 144>>>(y2, cw2, cx, c8x);

    gwc_volume_kernel<<<dim3(40, 8, 2), dim3(144, 2)>>>(g8x, out);
    cat_volume_kernel<<<(2 * 24 * cfg::Dd * cfg::HW + 255) / 256, 256>>>(c8x, out);
}

// round 5
// speedup vs baseline: 1.2186x; 1.2186x over previous
#include <cuda_runtime.h>
#include <cuda_bf16.h>
#include <cstdint>
#include <cstddef>

// ---------------------------------------------------------------------------
// Problem constants
// ---------------------------------------------------------------------------
namespace cfg {
constexpr int B   = 4;
constexpr int Hn  = 160, Wn = 288;      // input H, W
constexpr int HOo = 80,  WOo = 144;     // output H, W (stride 2)
constexpr int HW  = HOo * WOo;          // 11520
constexpr int HWin = Hn * Wn;           // 46080
constexpr int Dd  = 24;                 // disparity levels
constexpr int G_CI = 96, G_CO = 192;
constexpr int NCHUNK = 27;              // conv: 27 chunks of 32 k (tap-major)
constexpr int MT = 128;                 // pixels per CTA
}

// Scratch (static device globals — no allocation allowed)
__device__ float d_y1 [(size_t)cfg::B * cfg::G_CO * cfg::HW];   // 35.4 MB
__device__ float d_g8x[(size_t)cfg::B * cfg::G_CI * cfg::HW];   // 17.7 MB
__device__ float d_y2 [(size_t)cfg::B * 24 * cfg::HW];          //  4.4 MB
__device__ float d_c8x[(size_t)cfg::B * 12 * cfg::HW];          //  2.2 MB
__device__ float d_msk[(size_t)cfg::B * 144 * cfg::HW];         // 26.5 MB (gwc logits)
// Pre-split bf16 conv weights: [chunk 27][nhalf 2] blobs of 15360B
__device__ uint4 d_wB[(size_t)cfg::NCHUNK * 2 * 960];
// Pre-split bf16 mask weights: [chunk 6] blobs of 23040B (hi 144x40 | lo 144x40)
__device__ uint4 d_wM[(size_t)6 * 1440];

// ---------------------------------------------------------------------------
// PTX helpers (sm_80-compatible only: ldmatrix / mma.sync / cp.async)
// ---------------------------------------------------------------------------
__device__ __forceinline__ uint32_t smem_u32(const void* p) {
    uint32_t a;
    asm("{ .reg .u64 t; cvta.to.shared.u64 t, %1; cvt.u32.u64 %0, t; }" : "=r"(a) : "l"(p));
    return a;
}
__device__ __forceinline__ void ldsm4(uint32_t* r, uint32_t addr) {
    asm volatile("ldmatrix.sync.aligned.m8n8.x4.shared.b16 {%0,%1,%2,%3}, [%4];"
        : "=r"(r[0]), "=r"(r[1]), "=r"(r[2]), "=r"(r[3]) : "r"(addr));
}
__device__ __forceinline__ void mma_bf16(float* c, const uint32_t* a, const uint32_t* b) {
    asm volatile(
        "mma.sync.aligned.m16n8k16.row.col.f32.bf16.bf16.f32 "
        "{%0,%1,%2,%3}, {%4,%5,%6,%7}, {%8,%9}, {%0,%1,%2,%3};"
        : "+f"(c[0]), "+f"(c[1]), "+f"(c[2]), "+f"(c[3])
        : "r"(a[0]), "r"(a[1]), "r"(a[2]), "r"(a[3]), "r"(b[0]), "r"(b[1]));
}
#define CP_ASYNC16(dst, src) \
    asm volatile("cp.async.cg.shared.global [%0], [%1], 16;" :: "r"(dst), "l"(src) : "memory")
#define CP_COMMIT()  asm volatile("cp.async.commit_group;" ::: "memory")
#define CP_WAIT0()   asm volatile("cp.async.wait_group 0;" ::: "memory")

__device__ __forceinline__ void bf16_split(float v, uint16_t& h, uint16_t& l) {
    __nv_bfloat16 hb = __float2bfloat16_rn(v);
    __nv_bfloat16 lb = __float2bfloat16_rn(v - __bfloat162float(hb));
    h = __bfloat16_as_ushort(hb);
    l = __bfloat16_as_ushort(lb);
}

// ---------------------------------------------------------------------------
// Kernel 0a: conv weight prep. chunk = tap*3 + ci/32; rows padded to 40 bf16.
// ---------------------------------------------------------------------------
__global__ void wprep_kernel(const float* __restrict__ w) {
    using namespace cfg;
    int idx = blockIdx.x * blockDim.x + threadIdx.x;
    if (idx >= NCHUNK * 192 * 32) return;
    int k = idx & 31, co = (idx >> 5) % 192, c = idx / (32 * 192);
    int tap = c / 3, ci = (c % 3) * 32 + k;
    float v = w[(size_t)(co * G_CI + ci) * 9 + tap];
    uint16_t hi, lo; bf16_split(v, hi, lo);
    uint16_t* blob = (uint16_t*)d_wB + (size_t)(c * 2 + co / 96) * 7680;
    int col = co % 96;
    blob[col * 40 + k]        = hi;
    blob[3840 + col * 40 + k] = lo;
}

// ---------------------------------------------------------------------------
// Kernel 0b: gwc mask (1x1) weight prep. 6 chunks of 32 k; rows 40 bf16.
// ---------------------------------------------------------------------------
__global__ void wprep2_kernel(const float* __restrict__ w2) {
    using namespace cfg;
    int idx = blockIdx.x * blockDim.x + threadIdx.x;
    if (idx >= 6 * 144 * 32) return;
    int k = idx & 31, co = (idx >> 5) % 144, c = idx / (32 * 144);
    int ci = c * 32 + k;
    float v = w2[(size_t)co * 192 + ci];
    uint16_t hi, lo; bf16_split(v, hi, lo);
    uint16_t* blob = (uint16_t*)d_wM + (size_t)c * 11520;
    blob[co * 40 + k]        = hi;
    blob[5760 + co * 40 + k] = lo;
}

// ---------------------------------------------------------------------------
// Kernel 1: conv3x3 s2 p1 (96->192) + BN + leakyReLU, implicit GEMM,
// mma.sync bf16 hi/lo (3-pass). CTA: 128px x 96co, 8 warps (4Mx2N).
// (round-3 version: scalar-store epilogue, known good)
// ---------------------------------------------------------------------------
static constexpr int BUF_STRIDE = 35840;
static constexpr int SM_BN      = 2 * BUF_STRIDE;         // 71680
static constexpr int SM_CONV    = SM_BN + 768;            // 72448

__global__ void __launch_bounds__(256, 2)
conv_gwc_mma(const float* __restrict__ x,
             const float* __restrict__ bng, const float* __restrict__ bnb,
             const float* __restrict__ bnm, const float* __restrict__ bnv,
             float* __restrict__ y)
{
    using namespace cfg;
    extern __shared__ char smem[];
    const uint32_t sb = smem_u32(smem);
    const int t = threadIdx.x, lane = t & 31, wid = t >> 5;
    const int wm = wid & 3, wn = wid >> 2;

    float* sc_s = (float*)(smem + SM_BN);
    float* bi_s = (float*)(smem + SM_BN + 384);
    if (t < 96) {
        const int co = blockIdx.y * 96 + t;
        const float sc = bng[co] * rsqrtf(bnv[co] + 1e-5f);
        sc_s[t] = sc;
        bi_s[t] = bnb[co] - bnm[co] * sc;
    }

    const int pl = t & 127, khalf = t >> 7;
    const int p  = blockIdx.x * MT + pl;
    const int b  = p / HW;
    const int q  = p - b * HW;
    const int ho = q / WOo, wo = q - ho * WOo;
    const float* xb = x + (size_t)b * G_CI * HWin;

    const uint32_t a_off = (uint32_t)((lane & 7) + ((lane >> 3) & 1) * 8) * 80
                         + ((lane >> 4) << 4);
    const uint32_t b_off = (uint32_t)(((lane >> 4) * 8) + (lane & 7)) * 80
                         + (((lane >> 3) & 1) << 4);

    float acc[2][6][4];
    #pragma unroll
    for (int i = 0; i < 2; i++)
        #pragma unroll
        for (int j = 0; j < 6; j++)
            #pragma unroll
            for (int r = 0; r < 4; r++) acc[i][j][r] = 0.f;

    auto ldgA = [&](int c, float* v) {
        const int tap = c / 3, dy = tap / 3, dx = tap - dy * 3;
        const int ci0 = (c - tap * 3) * 32 + khalf * 16;
        const int h2 = 2 * ho - 1 + dy, w2 = 2 * wo - 1 + dx;
        const bool vr = ((unsigned)h2 < (unsigned)Hn) && ((unsigned)w2 < (unsigned)Wn);
        const float* xp = xb + (size_t)h2 * Wn + w2 + (size_t)ci0 * HWin;
        #pragma unroll
        for (int i = 0; i < 16; i++) v[i] = vr ? xp[(size_t)i * HWin] : 0.f;
    };
    auto stsA = [&](uint32_t bufb, const float* v) {
        uint32_t hp[8], lp[8];
        #pragma unroll
        for (int i = 0; i < 8; i++) {
            uint16_t h0, l0, h1, l1;
            bf16_split(v[2*i], h0, l0);
            bf16_split(v[2*i+1], h1, l1);
            hp[i] = (uint32_t)h0 | ((uint32_t)h1 << 16);
            lp[i] = (uint32_t)l0 | ((uint32_t)l1 << 16);
        }
        const uint32_t off = (uint32_t)pl * 80 + khalf * 32;
        *(uint4*)(smem + bufb + off)           = make_uint4(hp[0], hp[1], hp[2], hp[3]);
        *(uint4*)(smem + bufb + off + 16)      = make_uint4(hp[4], hp[5], hp[6], hp[7]);
        *(uint4*)(smem + bufb + 10240 + off)      = make_uint4(lp[0], lp[1], lp[2], lp[3]);
        *(uint4*)(smem + bufb + 10240 + off + 16) = make_uint4(lp[4], lp[5], lp[6], lp[7]);
    };
    auto cpB = [&](int c, uint32_t bufb) {
        const char* src = (const char*)d_wB + (size_t)(c * 2 + blockIdx.y) * 15360;
        const uint32_t dst = sb + bufb + 20480;
        #pragma unroll
        for (int j = t; j < 960; j += 256)
            CP_ASYNC16(dst + j * 16, src + (size_t)j * 16);
        CP_COMMIT();
    };

    {
        cpB(0, 0);
        float v0[16];
        ldgA(0, v0);
        stsA(0, v0);
        CP_WAIT0();
    }
    __syncthreads();

    float vnext[16];
    for (int c = 0; c < NCHUNK; c++) {
        const uint32_t bufb  = (uint32_t)(c & 1) * BUF_STRIDE;
        const uint32_t nbufb = (uint32_t)((c + 1) & 1) * BUF_STRIDE;
        const bool more = (c + 1 < NCHUNK);
        if (more) { cpB(c + 1, nbufb); ldgA(c + 1, vnext); }

        const uint32_t Ah = sb + bufb, Al = Ah + 10240;
        const uint32_t Bh = sb + bufb + 20480, Bl = Bh + 7680;
        #pragma unroll
        for (int ks = 0; ks < 2; ks++) {
            uint32_t ah[2][4], al[2][4], bb[3][4];
            #pragma unroll
            for (int ma = 0; ma < 2; ma++) {
                const uint32_t ro = (uint32_t)(wm * 32 + ma * 16) * 80 + ks * 32 + a_off;
                ldsm4(ah[ma], Ah + ro);
                ldsm4(al[ma], Al + ro);
            }
            #pragma unroll
            for (int n2 = 0; n2 < 3; n2++) {
                const uint32_t ro = (uint32_t)(wn * 48 + n2 * 16) * 80 + ks * 32 + b_off;
                ldsm4(bb[n2], Bh + ro);
            }
            #pragma unroll
            for (int ma = 0; ma < 2; ma++)
                #pragma unroll
                for (int n2 = 0; n2 < 3; n2++) {
                    mma_bf16(acc[ma][2*n2],   ah[ma], bb[n2]);
                    mma_bf16(acc[ma][2*n2+1], ah[ma], bb[n2] + 2);
                    mma_bf16(acc[ma][2*n2],   al[ma], bb[n2]);
                    mma_bf16(acc[ma][2*n2+1], al[ma], bb[n2] + 2);
                }
            #pragma unroll
            for (int n2 = 0; n2 < 3; n2++) {
                const uint32_t ro = (uint32_t)(wn * 48 + n2 * 16) * 80 + ks * 32 + b_off;
                ldsm4(bb[n2], Bl + ro);
            }
            #pragma unroll
            for (int ma = 0; ma < 2; ma++)
                #pragma unroll
                for (int n2 = 0; n2 < 3; n2++) {
                    mma_bf16(acc[ma][2*n2],   ah[ma], bb[n2]);
                    mma_bf16(acc[ma][2*n2+1], ah[ma], bb[n2] + 2);
                }
        }

        if (more) { stsA(nbufb, vnext); CP_WAIT0(); }
        __syncthreads();
    }

    // ---- epilogue: BN + leaky relu, scalar stores (round-3) ----
    {
        const int bt = (blockIdx.x * MT) / HW;          // tile never straddles b
        const int q0 = blockIdx.x * MT - bt * HW;
        float* yb = y + (size_t)bt * G_CO * HW + q0;
        const int t4 = lane >> 2, tp = (lane & 3) * 2;
        #pragma unroll
        for (int ma = 0; ma < 2; ma++) {
            const int r = wm * 32 + ma * 16 + t4;
            #pragma unroll
            for (int na = 0; na < 6; na++) {
                const int lc = wn * 48 + na * 8 + tp;
                const int co = blockIdx.y * 96 + lc;
                const float s0 = sc_s[lc], b0 = bi_s[lc];
                const float s1 = sc_s[lc + 1], b1 = bi_s[lc + 1];
                float v00 = fmaf(acc[ma][na][0], s0, b0);
                float v01 = fmaf(acc[ma][na][1], s1, b1);
                float v10 = fmaf(acc[ma][na][2], s0, b0);
                float v11 = fmaf(acc[ma][na][3], s1, b1);
                v00 = (v00 >= 0.f) ? v00 : 0.1f * v00;
                v01 = (v01 >= 0.f) ? v01 : 0.1f * v01;
                v10 = (v10 >= 0.f) ? v10 : 0.1f * v10;
                v11 = (v11 >= 0.f) ? v11 : 0.1f * v11;
                yb[(size_t)co * HW + r]           = v00;
                yb[(size_t)(co + 1) * HW + r]     = v01;
                yb[(size_t)co * HW + r + 8]       = v10;
                yb[(size_t)(co + 1) * HW + r + 8] = v11;
            }
        }
    }
}

// ---------------------------------------------------------------------------
// Kernel 2: gwc mask logits GEMM: msk[144, px] = w2[144,192] . y1[192, px].
// CTA: 128 px x 144 co, 12 warps (4M x 3N), warp tile 32x48.
// Same bf16 hi/lo 3-pass as the conv; K = 6 chunks of 32.
// smem: 2 x [Ahi 10240 | Alo 10240 | Bhi 11520 | Blo 11520] = 87040
// ---------------------------------------------------------------------------
static constexpr int LBUF   = 43520;
static constexpr int SM_LOG = 2 * LBUF;                   // 87040

__global__ void __launch_bounds__(384, 1)
gemm_logits_mma(const float* __restrict__ y, float* __restrict__ msk)
{
    using namespace cfg;
    extern __shared__ char smem[];
    const uint32_t sb = smem_u32(smem);
    const int t = threadIdx.x, lane = t & 31, wid = t >> 5;
    const int wm = wid & 3, wn = wid >> 2;        // wn 0..2

    const int pl = t & 127, kh = t >> 7;          // kh 0..2; only kh<2 stage A
    const int p  = blockIdx.x * MT + pl;
    const int b  = p / HW;
    const int q  = p - b * HW;
    const float* yb = y + (size_t)b * G_CO * HW + q;

    const uint32_t a_off = (uint32_t)((lane & 7) + ((lane >> 3) & 1) * 8) * 80
                         + ((lane >> 4) << 4);
    const uint32_t b_off = (uint32_t)(((lane >> 4) * 8) + (lane & 7)) * 80
                         + (((lane >> 3) & 1) << 4);

    float acc[2][6][4];
    #pragma unroll
    for (int i = 0; i < 2; i++)
        #pragma unroll
        for (int j = 0; j < 6; j++)
            #pragma unroll
            for (int r = 0; r < 4; r++) acc[i][j][r] = 0.f;

    auto ldgA = [&](int c, float* v) {
        const float* yp = yb + (size_t)(c * 32 + kh * 16) * HW;
        #pragma unroll
        for (int i = 0; i < 16; i++) v[i] = yp[(size_t)i * HW];
    };
    auto stsA = [&](uint32_t bufb, const float* v) {
        uint32_t hp[8], lp[8];
        #pragma unroll
        for (int i = 0; i < 8; i++) {
            uint16_t h0, l0, h1, l1;
            bf16_split(v[2*i], h0, l0);
            bf16_split(v[2*i+1], h1, l1);
            hp[i] = (uint32_t)h0 | ((uint32_t)h1 << 16);
            lp[i] = (uint32_t)l0 | ((uint32_t)l1 << 16);
        }
        const uint32_t off = (uint32_t)pl * 80 + kh * 32;
        *(uint4*)(smem + bufb + off)           = make_uint4(hp[0], hp[1], hp[2], hp[3]);
        *(uint4*)(smem + bufb + off + 16)      = make_uint4(hp[4], hp[5], hp[6], hp[7]);
        *(uint4*)(smem + bufb + 10240 + off)      = make_uint4(lp[0], lp[1], lp[2], lp[3]);
        *(uint4*)(smem + bufb + 10240 + off + 16) = make_uint4(lp[4], lp[5], lp[6], lp[7]);
    };
    auto cpB = [&](int c, uint32_t bufb) {
        const char* src = (const char*)d_wM + (size_t)c * 23040;
        const uint32_t dst = sb + bufb + 20480;
        for (int j = t; j < 1440; j += 384)
            CP_ASYNC16(dst + j * 16, src + (size_t)j * 16);
        CP_COMMIT();
    };

    {
        cpB(0, 0);
        if (kh < 2) {
            float v0[16];
            ldgA(0, v0);
            stsA(0, v0);
        }
        CP_WAIT0();
    }
    __syncthreads();

    float vnext[16];
    for (int c = 0; c < 6; c++) {
        const uint32_t bufb  = (uint32_t)(c & 1) * LBUF;
        const uint32_t nbufb = (uint32_t)((c + 1) & 1) * LBUF;
        const bool more = (c + 1 < 6);
        if (more) { cpB(c + 1, nbufb); if (kh < 2) ldgA(c + 1, vnext); }

        const uint32_t Ah = sb + bufb, Al = Ah + 10240;
        const uint32_t Bh = sb + bufb + 20480, Bl = Bh + 11520;
        #pragma unroll
        for (int ks = 0; ks < 2; ks++) {
            uint32_t ah[2][4], al[2][4], bb[3][4];
            #pragma unroll
            for (int ma = 0; ma < 2; ma++) {
                const uint32_t ro = (uint32_t)(wm * 32 + ma * 16) * 80 + ks * 32 + a_off;
                ldsm4(ah[ma], Ah + ro);
                ldsm4(al[ma], Al + ro);
            }
            #pragma unroll
            for (int n2 = 0; n2 < 3; n2++) {
                const uint32_t ro = (uint32_t)(wn * 48 + n2 * 16) * 80 + ks * 32 + b_off;
                ldsm4(bb[n2], Bh + ro);
            }
            #pragma unroll
            for (int ma = 0; ma < 2; ma++)
                #pragma unroll
                for (int n2 = 0; n2 < 3; n2++) {
                    mma_bf16(acc[ma][2*n2],   ah[ma], bb[n2]);
                    mma_bf16(acc[ma][2*n2+1], ah[ma], bb[n2] + 2);
                    mma_bf16(acc[ma][2*n2],   al[ma], bb[n2]);
                    mma_bf16(acc[ma][2*n2+1], al[ma], bb[n2] + 2);
                }
            #pragma unroll
            for (int n2 = 0; n2 < 3; n2++) {
                const uint32_t ro = (uint32_t)(wn * 48 + n2 * 16) * 80 + ks * 32 + b_off;
                ldsm4(bb[n2], Bl + ro);
            }
            #pragma unroll
            for (int ma = 0; ma < 2; ma++)
                #pragma unroll
                for (int n2 = 0; n2 < 3; n2++) {
                    mma_bf16(acc[ma][2*n2],   ah[ma], bb[n2]);
                    mma_bf16(acc[ma][2*n2+1], ah[ma], bb[n2] + 2);
                }
        }

        if (more) { if (kh < 2) stsA(nbufb, vnext); CP_WAIT0(); }
        __syncthreads();
    }

    // ---- epilogue: smem transpose -> coalesced float4 stores ----
    {
        float* ys = (float*)smem;               // [144 co][128 px]
        const int t4 = lane >> 2, tp = (lane & 3) * 2;
        #pragma unroll
        for (int ma = 0; ma < 2; ma++) {
            const int r = wm * 32 + ma * 16 + t4;
            #pragma unroll
            for (int na = 0; na < 6; na++) {
                const int lc = wn * 48 + na * 8 + tp;
                ys[(size_t)lc * 128 + r]            = acc[ma][na][0];
                ys[(size_t)(lc + 1) * 128 + r]      = acc[ma][na][1];
                ys[(size_t)lc * 128 + r + 8]        = acc[ma][na][2];
                ys[(size_t)(lc + 1) * 128 + r + 8]  = acc[ma][na][3];
            }
        }
        __syncthreads();
        const int bt = (blockIdx.x * MT) / HW;
        const int q0 = blockIdx.x * MT - bt * HW;
        float* mb = msk + (size_t)bt * 144 * HW + q0;
        #pragma unroll
        for (int i = 0; i < 12; i++) {
            const int idx = t + i * 384;        // co*32 + p4
            const int co = idx >> 5, p4 = idx & 31;
            *(float4*)(mb + (size_t)co * HW + p4 * 4) = *(float4*)&ys[(size_t)co * 128 + p4 * 4];
        }
    }
}

// ---------------------------------------------------------------------------
// Kernel 3: softmax over 9 taps + unfold-weighted sum (gwc), logits from msk.
// thread = (group g, quad q of 4 px). Logit reads are coalesced float4.
// ---------------------------------------------------------------------------
__global__ void __launch_bounds__(192)
softmax_unfold_gwc(const float* __restrict__ msk, const float* __restrict__ x,
                   float* __restrict__ out)
{
    using namespace cfg;
    const int ho  = blockIdx.y;
    const int b   = blockIdx.z;
    const int tid = threadIdx.x;
    const int q   = tid % 12;
    const int g   = tid / 12;
    const int px0 = blockIdx.x * 48 + q * 4;

    float lg[9][4];
    const float* mb = msk + ((size_t)(b * 144 + g * 9) * HOo + ho) * WOo + px0;
    #pragma unroll
    for (int j = 0; j < 9; j++) {
        float4 v = *(const float4*)(mb + (size_t)j * HW);
        lg[j][0] = v.x; lg[j][1] = v.y; lg[j][2] = v.z; lg[j][3] = v.w;
    }

    #pragma unroll
    for (int p = 0; p < 4; p++) {
        float mx = lg[0][p];
        #pragma unroll
        for (int j = 1; j < 9; j++) mx = fmaxf(mx, lg[j][p]);
        float s = 0.f;
        #pragma unroll
        for (int j = 0; j < 9; j++) { float e = expf(lg[j][p] - mx); lg[j][p] = e; s += e; }
        const float inv = 1.f / s;
        #pragma unroll
        for (int j = 0; j < 9; j++) lg[j][p] *= inv;
    }

    #pragma unroll
    for (int io = 0; io < 6; io++) {
        const int ch = io * 16 + g;
        const float* xc = x + (size_t)(b * G_CI + ch) * HWin;
        float o[4] = {0.f, 0.f, 0.f, 0.f};
        #pragma unroll
        for (int dy = 0; dy < 3; dy++) {
            const int h2 = 2 * ho + dy - 1;
            if ((unsigned)h2 < (unsigned)Hn) {
                const float* xr = xc + (size_t)h2 * Wn;
                const int wb = 2 * px0 - 1;
                float xv[9];
                #pragma unroll
                for (int k = 0; k < 9; k++) {
                    const int wi = wb + k;
                    xv[k] = ((unsigned)wi < (unsigned)Wn) ? xr[wi] : 0.f;
                }
                #pragma unroll
                for (int p = 0; p < 4; p++)
                    #pragma unroll
                    for (int dx = 0; dx < 3; dx++)
                        o[p] = fmaf(lg[dy * 3 + dx][p], xv[2 * p + dx], o[p]);
            }
        }
        *(float4*)(out + ((size_t)(b * G_CI + ch) * HOo + ho) * WOo + px0) =
            make_float4(o[0], o[1], o[2], o[3]);
    }
}

// ---------------------------------------------------------------------------
// Direct fp32 conv (tiny cat path: 12->24)
// ---------------------------------------------------------------------------
template<int CI, int CO_T, int HO_T, int WO_T>
__global__ void __launch_bounds__(WO_T * (CO_T / 4))
conv3x3s2_bn_lrelu(const float* __restrict__ x, const float* __restrict__ wgt,
                   const float* __restrict__ bng, const float* __restrict__ bnb,
                   const float* __restrict__ bnm, const float* __restrict__ bnv,
                   float* __restrict__ y, int CO, int tiles_x)
{
    using namespace cfg;
    constexpr int NTh  = WO_T * (CO_T / 4);
    constexpr int IN_H = 2 * HO_T + 1;
    constexpr int IN_W = 2 * WO_T + 1;

    __shared__ float xe[IN_H][WO_T + 2];
    __shared__ float xo[IN_H][WO_T + 1];
    __shared__ float ws[CO_T * 9];

    const int tx  = blockIdx.x % tiles_x;
    const int ty  = blockIdx.x / tiles_x;
    const int wo0 = tx * WO_T, ho0 = ty * HO_T;
    const int co0 = blockIdx.y * CO_T;
    const int b   = blockIdx.z;
    const int tid = threadIdx.x;
    const int px  = tid % WO_T;
    const int cg  = tid / WO_T;

    float acc[4][HO_T];
    #pragma unroll
    for (int j = 0; j < 4; j++)
        #pragma unroll
        for (int r = 0; r < HO_T; r++) acc[j][r] = 0.f;

    const float* xb = x + (size_t)b * CI * Hn * Wn;
    const int h_base = 2 * ho0 - 1, w_base = 2 * wo0 - 1;

    for (int ci = 0; ci < CI; ci++) {
        const float* xc = xb + (size_t)ci * Hn * Wn;
        for (int i = tid; i < IN_H * IN_W; i += NTh) {
            int r = i / IN_W, c = i - r * IN_W;
            int hh = h_base + r, ww = w_base + c;
            float v = 0.f;
            if ((unsigned)hh < (unsigned)Hn && (unsigned)ww < (unsigned)Wn)
                v = xc[hh * Wn + ww];
            if (c & 1) xo[r][c >> 1] = v; else xe[r][c >> 1] = v;
        }
        for (int i = tid; i < CO_T * 9; i += NTh)
            ws[i] = wgt[((size_t)(co0 + i / 9) * CI + ci) * 9 + (i % 9)];
        __syncthreads();

        float wr[4][9];
        #pragma unroll
        for (int j = 0; j < 4; j++)
            #pragma unroll
            for (int tt = 0; tt < 9; tt++)
                wr[j][tt] = ws[(cg * 4 + j) * 9 + tt];

        #pragma unroll
        for (int ir = 0; ir < IN_H; ir++) {
            const float x0 = xe[ir][px];
            const float x1 = xo[ir][px];
            const float x2 = xe[ir][px + 1];
            #pragma unroll
            for (int dy = 0; dy < 3; dy++) {
                const int rn = ir - dy;
                if ((rn & 1) == 0 && rn >= 0 && rn < 2 * HO_T) {
                    const int r = rn >> 1;
                    #pragma unroll
                    for (int j = 0; j < 4; j++) {
                        acc[j][r] = fmaf(x0, wr[j][dy * 3 + 0], acc[j][r]);
                        acc[j][r] = fmaf(x1, wr[j][dy * 3 + 1], acc[j][r]);
                        acc[j][r] = fmaf(x2, wr[j][dy * 3 + 2], acc[j][r]);
                    }
                }
            }
        }
        __syncthreads();
    }

    #pragma unroll
    for (int j = 0; j < 4; j++) {
        const int co = co0 + cg * 4 + j;
        const float sc = bng[co] * rsqrtf(bnv[co] + 1e-5f);
        const float bi = bnb[co] - bnm[co] * sc;
        #pragma unroll
        for (int r = 0; r < HO_T; r++) {
            float v = fmaf(acc[j][r], sc, bi);
            v = (v >= 0.f) ? v : 0.1f * v;
            y[((size_t)(b * CO + co) * HOo + (ho0 + r)) * WOo + wo0 + px] = v;
        }
    }
}

// ---------------------------------------------------------------------------
// Fused 1x1 conv -> softmax(9) -> unfold (round-3 version, cat path only)
// ---------------------------------------------------------------------------
template<int CI_X, int CIY, int G, int CPG, int QUADS>
__global__ void __launch_bounds__(G * QUADS)
mask_softmax_unfold(const float* __restrict__ y, const float* __restrict__ w2,
                    const float* __restrict__ x, float* __restrict__ out)
{
    using namespace cfg;
    const int wo0 = blockIdx.x * (QUADS * 4);
    const int ho  = blockIdx.y;
    const int b   = blockIdx.z;
    const int tid = threadIdx.x;
    const int q   = tid % QUADS;
    const int g   = tid / QUADS;
    const int px0 = wo0 + q * 4;

    float lg[9][4];
    #pragma unroll
    for (int j = 0; j < 9; j++)
        #pragma unroll
        for (int p = 0; p < 4; p++) lg[j][p] = 0.f;

    const size_t ybase = (size_t)b * CIY * HW + (size_t)ho * WOo + px0;
    const float* wg = w2 + (size_t)g * 9 * CIY;

    for (int c4 = 0; c4 < CIY; c4 += 4) {
        float4 yv0 = *(const float4*)(y + ybase + (size_t)(c4 + 0) * HW);
        float4 yv1 = *(const float4*)(y + ybase + (size_t)(c4 + 1) * HW);
        float4 yv2 = *(const float4*)(y + ybase + (size_t)(c4 + 2) * HW);
        float4 yv3 = *(const float4*)(y + ybase + (size_t)(c4 + 3) * HW);
        #pragma unroll
        for (int j = 0; j < 9; j++) {
            float4 wv = *(const float4*)(wg + j * CIY + c4);
            lg[j][0] += wv.x * yv0.x + wv.y * yv1.x + wv.z * yv2.x + wv.w * yv3.x;
            lg[j][1] += wv.x * yv0.y + wv.y * yv1.y + wv.z * yv2.y + wv.w * yv3.y;
            lg[j][2] += wv.x * yv0.z + wv.y * yv1.z + wv.z * yv2.z + wv.w * yv3.z;
            lg[j][3] += wv.x * yv0.w + wv.y * yv1.w + wv.z * yv2.w + wv.w * yv3.w;
        }
    }

    #pragma unroll
    for (int p = 0; p < 4; p++) {
        float mx = lg[0][p];
        #pragma unroll
        for (int j = 1; j < 9; j++) mx = fmaxf(mx, lg[j][p]);
        float s = 0.f;
        #pragma unroll
        for (int j = 0; j < 9; j++) { float e = expf(lg[j][p] - mx); lg[j][p] = e; s += e; }
        const float inv = 1.f / s;
        #pragma unroll
        for (int j = 0; j < 9; j++) lg[j][p] *= inv;
    }

    #pragma unroll
    for (int io = 0; io < CPG; io++) {
        const int ch = io * G + g;
        const float* xc = x + (size_t)(b * CI_X + ch) * Hn * Wn;
        float o[4] = {0.f, 0.f, 0.f, 0.f};
        #pragma unroll
        for (int dy = 0; dy < 3; dy++) {
            const int h2 = 2 * ho + dy - 1;
            if ((unsigned)h2 < (unsigned)Hn) {
                const float* xr = xc + (size_t)h2 * Wn;
                const int wb = 2 * px0 - 1;
                float xv[9];
                #pragma unroll
                for (int k = 0; k < 9; k++) {
                    const int wi = wb + k;
                    xv[k] = ((unsigned)wi < (unsigned)Wn) ? xr[wi] : 0.f;
                }
                #pragma unroll
                for (int p = 0; p < 4; p++)
                    #pragma unroll
                    for (int dx = 0; dx < 3; dx++)
                        o[p] = fmaf(lg[dy * 3 + dx][p], xv[2 * p + dx], o[p]);
            }
        }
        *(float4*)(out + ((size_t)(b * CI_X + ch) * HOo + ho) * WOo + px0) =
            make_float4(o[0], o[1], o[2], o[3]);
    }
}

// ---------------------------------------------------------------------------
// Cost volumes
// ---------------------------------------------------------------------------
__global__ void __launch_bounds__(288)
gwc_volume_kernel(const float* __restrict__ g8x, float* __restrict__ out)
{
    using namespace cfg;
    __shared__ float rs[2][12][WOo];
    const int h  = blockIdx.x * 2 + threadIdx.y;
    const int g  = blockIdx.y;
    const int b  = blockIdx.z;
    const int w  = threadIdx.x;
    const int hy = threadIdx.y;

    const float* rbase = g8x + ((size_t)((b + 2) * G_CI + g * 12) * HOo + h) * WOo;
    #pragma unroll
    for (int c = 0; c < 12; c++)
        rs[hy][c][w] = rbase[(size_t)c * HW + w];
    __syncthreads();

    const float* lbase = g8x + ((size_t)(b * G_CI + g * 12) * HOo + h) * WOo + w;
    float lr[12];
    #pragma unroll
    for (int c = 0; c < 12; c++) lr[c] = lbase[(size_t)c * HW];

    for (int d = 0; d < Dd; d++) {
        float s = 0.f;
        if (w >= d) {
            #pragma unroll
            for (int c = 0; c < 12; c++) s = fmaf(lr[c], rs[hy][c][w - d], s);
            s *= (1.f / 12.f);
        }
        out[(((size_t)(b * 32 + g) * Dd + d) * HOo + h) * WOo + w] = s;
    }
}

__global__ void cat_volume_kernel(const float* __restrict__ c8x, float* __restrict__ out)
{
    using namespace cfg;
    const int idx = blockIdx.x * blockDim.x + threadIdx.x;
    constexpr int TOT = 2 * 24 * Dd * HW;
    if (idx >= TOT) return;
    int t = idx;
    const int w = t % WOo;  t /= WOo;
    const int h = t % HOo;  t /= HOo;
    const int d = t % Dd;   t /= Dd;
    const int cc = t % 24;
    const int b  = t / 24;

    float v = 0.f;
    if (w >= d) {
        if (cc < 12)
            v = c8x[((size_t)(b * 12 + cc) * HOo + h) * WOo + w];
        else
            v = c8x[((size_t)((b + 2) * 12 + (cc - 12)) * HOo + h) * WOo + (w - d)];
    }
    out[(((size_t)(b * 32 + 8 + cc) * Dd + d) * HOo + h) * WOo + w] = v;
}

// ---------------------------------------------------------------------------
// Launch
// ---------------------------------------------------------------------------
extern "C" void kernel_launch(void* const* d_in, const int* in_sizes, int n_in,
                              void* d_out, int out_size)
{
    const float* gx  = (const float*)d_in[0];
    const float* cx  = (const float*)d_in[1];
    const float* gw1 = (const float*)d_in[2];
    const float* gbg = (const float*)d_in[3];
    const float* gbb = (const float*)d_in[4];
    const float* gbm = (const float*)d_in[5];
    const float* gbv = (const float*)d_in[6];
    const float* gw2 = (const float*)d_in[7];
    const float* cw1 = (const float*)d_in[8];
    const float* cbg = (const float*)d_in[9];
    const float* cbb = (const float*)d_in[10];
    const float* cbm = (const float*)d_in[11];
    const float* cbv = (const float*)d_in[12];
    const float* cw2 = (const float*)d_in[13];
    float* out = (float*)d_out;

    float *y1, *g8x, *y2, *c8x, *msk;
    cudaGetSymbolAddress((void**)&y1,  d_y1);
    cudaGetSymbolAddress((void**)&g8x, d_g8x);
    cudaGetSymbolAddress((void**)&y2,  d_y2);
    cudaGetSymbolAddress((void**)&c8x, d_c8x);
    cudaGetSymbolAddress((void**)&msk, d_msk);

    cudaFuncSetAttribute(conv_gwc_mma, cudaFuncAttributeMaxDynamicSharedMemorySize, SM_CONV);
    cudaFuncSetAttribute(gemm_logits_mma, cudaFuncAttributeMaxDynamicSharedMemorySize, SM_LOG);

    wprep_kernel<<<(cfg::NCHUNK * 192 * 32 + 255) / 256, 256>>>(gw1);
    wprep2_kernel<<<(6 * 144 * 32 + 255) / 256, 256>>>(gw2);

    conv_gwc_mma<<<dim3(360, 2), 256, SM_CONV>>>(gx, gbg, gbb, gbm, gbv, y1);

    conv3x3s2_bn_lrelu<12, 24, 8, 48><<<dim3(30, 1, 4), 288>>>(
        cx, cw1, cbg, cbb, cbm, cbv, y2, 24, 3);

    gemm_logits_mma<<<360, 384, SM_LOG>>>(y1, msk);
    softmax_unfold_gwc<<<dim3(3, 80, 4), 192>>>(msk, gx, g8x);

    mask_softmax_unfold<12, 24, 12, 1, 12><<<dim3(3, 80, 4), 144>>>(y2, cw2, cx, c8x);

    gwc_volume_kernel<<<dim3(40, 8, 2), dim3(144, 2)>>>(g8x, out);
    cat_volume_kernel<<<(2 * 24 * cfg::Dd * cfg::HW + 255) / 256, 256>>>(c8x, out);
}

// round 6
// speedup vs baseline: 1.3521x; 1.1096x over previous
#include <cuda_runtime.h>
#include <cuda_bf16.h>
#include <cstdint>
#include <cstddef>

// ---------------------------------------------------------------------------
// Problem constants
// ---------------------------------------------------------------------------
namespace cfg {
constexpr int B   = 4;
constexpr int Hn  = 160, Wn = 288;      // input H, W
constexpr int HOo = 80,  WOo = 144;     // output H, W (stride 2)
constexpr int HW  = HOo * WOo;          // 11520
constexpr int HWin = Hn * Wn;           // 46080
constexpr int Dd  = 24;                 // disparity levels
constexpr int G_CI = 96, G_CO = 192;
constexpr int NCHUNK = 27;              // conv: 27 chunks of 32 k (tap-major)
constexpr int MT = 128;                 // pixels per CTA
}

// Scratch (static device globals — no allocation allowed)
__device__ float d_y1 [(size_t)cfg::B * cfg::G_CO * cfg::HW];   // 35.4 MB
__device__ float d_g8x[(size_t)cfg::B * cfg::G_CI * cfg::HW];   // 17.7 MB
__device__ float d_y2 [(size_t)cfg::B * 24 * cfg::HW];          //  4.4 MB
__device__ float d_c8x[(size_t)cfg::B * 12 * cfg::HW];          //  2.2 MB
__device__ float d_msk[(size_t)cfg::B * 144 * cfg::HW];         // 26.5 MB (gwc logits)
// Pre-split bf16 conv weights: [chunk 27][nhalf 2] blobs of 15360B
__device__ uint4 d_wB[(size_t)cfg::NCHUNK * 2 * 960];
// Pre-split bf16 mask weights: [chunk 6] blobs of 23040B (hi 144x40 | lo 144x40)
__device__ uint4 d_wM[(size_t)6 * 1440];

// ---------------------------------------------------------------------------
// PTX helpers (sm_80-compatible only: ldmatrix / mma.sync / cp.async)
// ---------------------------------------------------------------------------
__device__ __forceinline__ uint32_t smem_u32(const void* p) {
    uint32_t a;
    asm("{ .reg .u64 t; cvta.to.shared.u64 t, %1; cvt.u32.u64 %0, t; }" : "=r"(a) : "l"(p));
    return a;
}
__device__ __forceinline__ void ldsm4(uint32_t* r, uint32_t addr) {
    asm volatile("ldmatrix.sync.aligned.m8n8.x4.shared.b16 {%0,%1,%2,%3}, [%4];"
        : "=r"(r[0]), "=r"(r[1]), "=r"(r[2]), "=r"(r[3]) : "r"(addr));
}
__device__ __forceinline__ void mma_bf16(float* c, const uint32_t* a, const uint32_t* b) {
    asm volatile(
        "mma.sync.aligned.m16n8k16.row.col.f32.bf16.bf16.f32 "
        "{%0,%1,%2,%3}, {%4,%5,%6,%7}, {%8,%9}, {%0,%1,%2,%3};"
        : "+f"(c[0]), "+f"(c[1]), "+f"(c[2]), "+f"(c[3])
        : "r"(a[0]), "r"(a[1]), "r"(a[2]), "r"(a[3]), "r"(b[0]), "r"(b[1]));
}
#define CP_ASYNC16(dst, src) \
    asm volatile("cp.async.cg.shared.global [%0], [%1], 16;" :: "r"(dst), "l"(src) : "memory")
#define CP_COMMIT()  asm volatile("cp.async.commit_group;" ::: "memory")
#define CP_WAIT0()   asm volatile("cp.async.wait_group 0;" ::: "memory")

__device__ __forceinline__ void bf16_split(float v, uint16_t& h, uint16_t& l) {
    __nv_bfloat16 hb = __float2bfloat16_rn(v);
    __nv_bfloat16 lb = __float2bfloat16_rn(v - __bfloat162float(hb));
    h = __bfloat16_as_ushort(hb);
    l = __bfloat16_as_ushort(lb);
}

// ---------------------------------------------------------------------------
// Kernel 0a: conv weight prep. chunk = tap*3 + ci/32; rows padded to 40 bf16.
// ---------------------------------------------------------------------------
__global__ void wprep_kernel(const float* __restrict__ w) {
    using namespace cfg;
    int idx = blockIdx.x * blockDim.x + threadIdx.x;
    if (idx >= NCHUNK * 192 * 32) return;
    int k = idx & 31, co = (idx >> 5) % 192, c = idx / (32 * 192);
    int tap = c / 3, ci = (c % 3) * 32 + k;
    float v = w[(size_t)(co * G_CI + ci) * 9 + tap];
    uint16_t hi, lo; bf16_split(v, hi, lo);
    uint16_t* blob = (uint16_t*)d_wB + (size_t)(c * 2 + co / 96) * 7680;
    int col = co % 96;
    blob[col * 40 + k]        = hi;
    blob[3840 + col * 40 + k] = lo;
}

// ---------------------------------------------------------------------------
// Kernel 0b: gwc mask (1x1) weight prep. 6 chunks of 32 k; rows 40 bf16.
// ---------------------------------------------------------------------------
__global__ void wprep2_kernel(const float* __restrict__ w2) {
    using namespace cfg;
    int idx = blockIdx.x * blockDim.x + threadIdx.x;
    if (idx >= 6 * 144 * 32) return;
    int k = idx & 31, co = (idx >> 5) % 144, c = idx / (32 * 144);
    int ci = c * 32 + k;
    float v = w2[(size_t)co * 192 + ci];
    uint16_t hi, lo; bf16_split(v, hi, lo);
    uint16_t* blob = (uint16_t*)d_wM + (size_t)c * 11520;
    blob[co * 40 + k]        = hi;
    blob[5760 + co * 40 + k] = lo;
}

// ---------------------------------------------------------------------------
// Kernel 1: conv3x3 s2 p1 (96->192) + BN + leakyReLU, implicit GEMM,
// mma.sync bf16 hi/lo (3-pass). CTA: 128px x 96co, 8 warps (4Mx2N).
// ---------------------------------------------------------------------------
static constexpr int BUF_STRIDE = 35840;
static constexpr int SM_BN      = 2 * BUF_STRIDE;         // 71680
static constexpr int SM_CONV    = SM_BN + 768;            // 72448

__global__ void __launch_bounds__(256, 2)
conv_gwc_mma(const float* __restrict__ x,
             const float* __restrict__ bng, const float* __restrict__ bnb,
             const float* __restrict__ bnm, const float* __restrict__ bnv,
             float* __restrict__ y)
{
    using namespace cfg;
    extern __shared__ char smem[];
    const uint32_t sb = smem_u32(smem);
    const int t = threadIdx.x, lane = t & 31, wid = t >> 5;
    const int wm = wid & 3, wn = wid >> 2;

    float* sc_s = (float*)(smem + SM_BN);
    float* bi_s = (float*)(smem + SM_BN + 384);
    if (t < 96) {
        const int co = blockIdx.y * 96 + t;
        const float sc = bng[co] * rsqrtf(bnv[co] + 1e-5f);
        sc_s[t] = sc;
        bi_s[t] = bnb[co] - bnm[co] * sc;
    }

    const int pl = t & 127, khalf = t >> 7;
    const int p  = blockIdx.x * MT + pl;
    const int b  = p / HW;
    const int q  = p - b * HW;
    const int ho = q / WOo, wo = q - ho * WOo;
    const float* xb = x + (size_t)b * G_CI * HWin;

    const uint32_t a_off = (uint32_t)((lane & 7) + ((lane >> 3) & 1) * 8) * 80
                         + ((lane >> 4) << 4);
    const uint32_t b_off = (uint32_t)(((lane >> 4) * 8) + (lane & 7)) * 80
                         + (((lane >> 3) & 1) << 4);

    float acc[2][6][4];
    #pragma unroll
    for (int i = 0; i < 2; i++)
        #pragma unroll
        for (int j = 0; j < 6; j++)
            #pragma unroll
            for (int r = 0; r < 4; r++) acc[i][j][r] = 0.f;

    auto ldgA = [&](int c, float* v) {
        const int tap = c / 3, dy = tap / 3, dx = tap - dy * 3;
        const int ci0 = (c - tap * 3) * 32 + khalf * 16;
        const int h2 = 2 * ho - 1 + dy, w2 = 2 * wo - 1 + dx;
        const bool vr = ((unsigned)h2 < (unsigned)Hn) && ((unsigned)w2 < (unsigned)Wn);
        const float* xp = xb + (size_t)h2 * Wn + w2 + (size_t)ci0 * HWin;
        #pragma unroll
        for (int i = 0; i < 16; i++) v[i] = vr ? xp[(size_t)i * HWin] : 0.f;
    };
    auto stsA = [&](uint32_t bufb, const float* v) {
        uint32_t hp[8], lp[8];
        #pragma unroll
        for (int i = 0; i < 8; i++) {
            uint16_t h0, l0, h1, l1;
            bf16_split(v[2*i], h0, l0);
            bf16_split(v[2*i+1], h1, l1);
            hp[i] = (uint32_t)h0 | ((uint32_t)h1 << 16);
            lp[i] = (uint32_t)l0 | ((uint32_t)l1 << 16);
        }
        const uint32_t off = (uint32_t)pl * 80 + khalf * 32;
        *(uint4*)(smem + bufb + off)           = make_uint4(hp[0], hp[1], hp[2], hp[3]);
        *(uint4*)(smem + bufb + off + 16)      = make_uint4(hp[4], hp[5], hp[6], hp[7]);
        *(uint4*)(smem + bufb + 10240 + off)      = make_uint4(lp[0], lp[1], lp[2], lp[3]);
        *(uint4*)(smem + bufb + 10240 + off + 16) = make_uint4(lp[4], lp[5], lp[6], lp[7]);
    };
    auto cpB = [&](int c, uint32_t bufb) {
        const char* src = (const char*)d_wB + (size_t)(c * 2 + blockIdx.y) * 15360;
        const uint32_t dst = sb + bufb + 20480;
        #pragma unroll
        for (int j = t; j < 960; j += 256)
            CP_ASYNC16(dst + j * 16, src + (size_t)j * 16);
        CP_COMMIT();
    };

    {
        cpB(0, 0);
        float v0[16];
        ldgA(0, v0);
        stsA(0, v0);
        CP_WAIT0();
    }
    __syncthreads();

    float vnext[16];
    for (int c = 0; c < NCHUNK; c++) {
        const uint32_t bufb  = (uint32_t)(c & 1) * BUF_STRIDE;
        const uint32_t nbufb = (uint32_t)((c + 1) & 1) * BUF_STRIDE;
        const bool more = (c + 1 < NCHUNK);
        if (more) { cpB(c + 1, nbufb); ldgA(c + 1, vnext); }

        const uint32_t Ah = sb + bufb, Al = Ah + 10240;
        const uint32_t Bh = sb + bufb + 20480, Bl = Bh + 7680;
        #pragma unroll
        for (int ks = 0; ks < 2; ks++) {
            uint32_t ah[2][4], al[2][4], bb[3][4];
            #pragma unroll
            for (int ma = 0; ma < 2; ma++) {
                const uint32_t ro = (uint32_t)(wm * 32 + ma * 16) * 80 + ks * 32 + a_off;
                ldsm4(ah[ma], Ah + ro);
                ldsm4(al[ma], Al + ro);
            }
            #pragma unroll
            for (int n2 = 0; n2 < 3; n2++) {
                const uint32_t ro = (uint32_t)(wn * 48 + n2 * 16) * 80 + ks * 32 + b_off;
                ldsm4(bb[n2], Bh + ro);
            }
            #pragma unroll
            for (int ma = 0; ma < 2; ma++)
                #pragma unroll
                for (int n2 = 0; n2 < 3; n2++) {
                    mma_bf16(acc[ma][2*n2],   ah[ma], bb[n2]);
                    mma_bf16(acc[ma][2*n2+1], ah[ma], bb[n2] + 2);
                    mma_bf16(acc[ma][2*n2],   al[ma], bb[n2]);
                    mma_bf16(acc[ma][2*n2+1], al[ma], bb[n2] + 2);
                }
            #pragma unroll
            for (int n2 = 0; n2 < 3; n2++) {
                const uint32_t ro = (uint32_t)(wn * 48 + n2 * 16) * 80 + ks * 32 + b_off;
                ldsm4(bb[n2], Bl + ro);
            }
            #pragma unroll
            for (int ma = 0; ma < 2; ma++)
                #pragma unroll
                for (int n2 = 0; n2 < 3; n2++) {
                    mma_bf16(acc[ma][2*n2],   ah[ma], bb[n2]);
                    mma_bf16(acc[ma][2*n2+1], ah[ma], bb[n2] + 2);
                }
        }

        if (more) { stsA(nbufb, vnext); CP_WAIT0(); }
        __syncthreads();
    }

    // ---- epilogue: BN + leaky relu, scalar stores ----
    {
        const int bt = (blockIdx.x * MT) / HW;          // tile never straddles b
        const int q0 = blockIdx.x * MT - bt * HW;
        float* yb = y + (size_t)bt * G_CO * HW + q0;
        const int t4 = lane >> 2, tp = (lane & 3) * 2;
        #pragma unroll
        for (int ma = 0; ma < 2; ma++) {
            const int r = wm * 32 + ma * 16 + t4;
            #pragma unroll
            for (int na = 0; na < 6; na++) {
                const int lc = wn * 48 + na * 8 + tp;
                const int co = blockIdx.y * 96 + lc;
                const float s0 = sc_s[lc], b0 = bi_s[lc];
                const float s1 = sc_s[lc + 1], b1 = bi_s[lc + 1];
                float v00 = fmaf(acc[ma][na][0], s0, b0);
                float v01 = fmaf(acc[ma][na][1], s1, b1);
                float v10 = fmaf(acc[ma][na][2], s0, b0);
                float v11 = fmaf(acc[ma][na][3], s1, b1);
                v00 = (v00 >= 0.f) ? v00 : 0.1f * v00;
                v01 = (v01 >= 0.f) ? v01 : 0.1f * v01;
                v10 = (v10 >= 0.f) ? v10 : 0.1f * v10;
                v11 = (v11 >= 0.f) ? v11 : 0.1f * v11;
                yb[(size_t)co * HW + r]           = v00;
                yb[(size_t)(co + 1) * HW + r]     = v01;
                yb[(size_t)co * HW + r + 8]       = v10;
                yb[(size_t)(co + 1) * HW + r + 8] = v11;
            }
        }
    }
}

// ---------------------------------------------------------------------------
// Kernel 2: gwc mask logits GEMM: msk[144, px] = w2[144,192] . y1[192, px].
// CTA: 128 px x 144 co, 12 warps (4M x 3N), warp tile 32x48.
// ---------------------------------------------------------------------------
static constexpr int LBUF   = 43520;
static constexpr int SM_LOG = 2 * LBUF;                   // 87040

__global__ void __launch_bounds__(384, 1)
gemm_logits_mma(const float* __restrict__ y, float* __restrict__ msk)
{
    using namespace cfg;
    extern __shared__ char smem[];
    const uint32_t sb = smem_u32(smem);
    const int t = threadIdx.x, lane = t & 31, wid = t >> 5;
    const int wm = wid & 3, wn = wid >> 2;        // wn 0..2

    const int pl = t & 127, kh = t >> 7;          // kh 0..2; only kh<2 stage A
    const int p  = blockIdx.x * MT + pl;
    const int b  = p / HW;
    const int q  = p - b * HW;
    const float* yb = y + (size_t)b * G_CO * HW + q;

    const uint32_t a_off = (uint32_t)((lane & 7) + ((lane >> 3) & 1) * 8) * 80
                         + ((lane >> 4) << 4);
    const uint32_t b_off = (uint32_t)(((lane >> 4) * 8) + (lane & 7)) * 80
                         + (((lane >> 3) & 1) << 4);

    float acc[2][6][4];
    #pragma unroll
    for (int i = 0; i < 2; i++)
        #pragma unroll
        for (int j = 0; j < 6; j++)
            #pragma unroll
            for (int r = 0; r < 4; r++) acc[i][j][r] = 0.f;

    auto ldgA = [&](int c, float* v) {
        const float* yp = yb + (size_t)(c * 32 + kh * 16) * HW;
        #pragma unroll
        for (int i = 0; i < 16; i++) v[i] = yp[(size_t)i * HW];
    };
    auto stsA = [&](uint32_t bufb, const float* v) {
        uint32_t hp[8], lp[8];
        #pragma unroll
        for (int i = 0; i < 8; i++) {
            uint16_t h0, l0, h1, l1;
            bf16_split(v[2*i], h0, l0);
            bf16_split(v[2*i+1], h1, l1);
            hp[i] = (uint32_t)h0 | ((uint32_t)h1 << 16);
            lp[i] = (uint32_t)l0 | ((uint32_t)l1 << 16);
        }
        const uint32_t off = (uint32_t)pl * 80 + kh * 32;
        *(uint4*)(smem + bufb + off)           = make_uint4(hp[0], hp[1], hp[2], hp[3]);
        *(uint4*)(smem + bufb + off + 16)      = make_uint4(hp[4], hp[5], hp[6], hp[7]);
        *(uint4*)(smem + bufb + 10240 + off)      = make_uint4(lp[0], lp[1], lp[2], lp[3]);
        *(uint4*)(smem + bufb + 10240 + off + 16) = make_uint4(lp[4], lp[5], lp[6], lp[7]);
    };
    auto cpB = [&](int c, uint32_t bufb) {
        const char* src = (const char*)d_wM + (size_t)c * 23040;
        const uint32_t dst = sb + bufb + 20480;
        for (int j = t; j < 1440; j += 384)
            CP_ASYNC16(dst + j * 16, src + (size_t)j * 16);
        CP_COMMIT();
    };

    {
        cpB(0, 0);
        if (kh < 2) {
            float v0[16];
            ldgA(0, v0);
            stsA(0, v0);
        }
        CP_WAIT0();
    }
    __syncthreads();

    float vnext[16];
    for (int c = 0; c < 6; c++) {
        const uint32_t bufb  = (uint32_t)(c & 1) * LBUF;
        const uint32_t nbufb = (uint32_t)((c + 1) & 1) * LBUF;
        const bool more = (c + 1 < 6);
        if (more) { cpB(c + 1, nbufb); if (kh < 2) ldgA(c + 1, vnext); }

        const uint32_t Ah = sb + bufb, Al = Ah + 10240;
        const uint32_t Bh = sb + bufb + 20480, Bl = Bh + 11520;
        #pragma unroll
        for (int ks = 0; ks < 2; ks++) {
            uint32_t ah[2][4], al[2][4], bb[3][4];
            #pragma unroll
            for (int ma = 0; ma < 2; ma++) {
                const uint32_t ro = (uint32_t)(wm * 32 + ma * 16) * 80 + ks * 32 + a_off;
                ldsm4(ah[ma], Ah + ro);
                ldsm4(al[ma], Al + ro);
            }
            #pragma unroll
            for (int n2 = 0; n2 < 3; n2++) {
                const uint32_t ro = (uint32_t)(wn * 48 + n2 * 16) * 80 + ks * 32 + b_off;
                ldsm4(bb[n2], Bh + ro);
            }
            #pragma unroll
            for (int ma = 0; ma < 2; ma++)
                #pragma unroll
                for (int n2 = 0; n2 < 3; n2++) {
                    mma_bf16(acc[ma][2*n2],   ah[ma], bb[n2]);
                    mma_bf16(acc[ma][2*n2+1], ah[ma], bb[n2] + 2);
                    mma_bf16(acc[ma][2*n2],   al[ma], bb[n2]);
                    mma_bf16(acc[ma][2*n2+1], al[ma], bb[n2] + 2);
                }
            #pragma unroll
            for (int n2 = 0; n2 < 3; n2++) {
                const uint32_t ro = (uint32_t)(wn * 48 + n2 * 16) * 80 + ks * 32 + b_off;
                ldsm4(bb[n2], Bl + ro);
            }
            #pragma unroll
            for (int ma = 0; ma < 2; ma++)
                #pragma unroll
                for (int n2 = 0; n2 < 3; n2++) {
                    mma_bf16(acc[ma][2*n2],   ah[ma], bb[n2]);
                    mma_bf16(acc[ma][2*n2+1], ah[ma], bb[n2] + 2);
                }
        }

        if (more) { if (kh < 2) stsA(nbufb, vnext); CP_WAIT0(); }
        __syncthreads();
    }

    // ---- epilogue: smem transpose -> coalesced float4 stores ----
    {
        float* ys = (float*)smem;               // [144 co][128 px]
        const int t4 = lane >> 2, tp = (lane & 3) * 2;
        #pragma unroll
        for (int ma = 0; ma < 2; ma++) {
            const int r = wm * 32 + ma * 16 + t4;
            #pragma unroll
            for (int na = 0; na < 6; na++) {
                const int lc = wn * 48 + na * 8 + tp;
                ys[(size_t)lc * 128 + r]            = acc[ma][na][0];
                ys[(size_t)(lc + 1) * 128 + r]      = acc[ma][na][1];
                ys[(size_t)lc * 128 + r + 8]        = acc[ma][na][2];
                ys[(size_t)(lc + 1) * 128 + r + 8]  = acc[ma][na][3];
            }
        }
        __syncthreads();
        const int bt = (blockIdx.x * MT) / HW;
        const int q0 = blockIdx.x * MT - bt * HW;
        float* mb = msk + (size_t)bt * 144 * HW + q0;
        #pragma unroll
        for (int i = 0; i < 12; i++) {
            const int idx = t + i * 384;        // co*32 + p4
            const int co = idx >> 5, p4 = idx & 31;
            *(float4*)(mb + (size_t)co * HW + p4 * 4) = *(float4*)&ys[(size_t)co * 128 + p4 * 4];
        }
    }
}

// ---------------------------------------------------------------------------
// Kernel 3: softmax over 9 taps + unfold-weighted sum (gwc), logits from msk.
// ---------------------------------------------------------------------------
__global__ void __launch_bounds__(192)
softmax_unfold_gwc(const float* __restrict__ msk, const float* __restrict__ x,
                   float* __restrict__ out)
{
    using namespace cfg;
    const int ho  = blockIdx.y;
    const int b   = blockIdx.z;
    const int tid = threadIdx.x;
    const int q   = tid % 12;
    const int g   = tid / 12;
    const int px0 = blockIdx.x * 48 + q * 4;

    float lg[9][4];
    const float* mb = msk + ((size_t)(b * 144 + g * 9) * HOo + ho) * WOo + px0;
    #pragma unroll
    for (int j = 0; j < 9; j++) {
        float4 v = *(const float4*)(mb + (size_t)j * HW);
        lg[j][0] = v.x; lg[j][1] = v.y; lg[j][2] = v.z; lg[j][3] = v.w;
    }

    #pragma unroll
    for (int p = 0; p < 4; p++) {
        float mx = lg[0][p];
        #pragma unroll
        for (int j = 1; j < 9; j++) mx = fmaxf(mx, lg[j][p]);
        float s = 0.f;
        #pragma unroll
        for (int j = 0; j < 9; j++) { float e = expf(lg[j][p] - mx); lg[j][p] = e; s += e; }
        const float inv = 1.f / s;
        #pragma unroll
        for (int j = 0; j < 9; j++) lg[j][p] *= inv;
    }

    #pragma unroll
    for (int io = 0; io < 6; io++) {
        const int ch = io * 16 + g;
        const float* xc = x + (size_t)(b * G_CI + ch) * HWin;
        float o[4] = {0.f, 0.f, 0.f, 0.f};
        #pragma unroll
        for (int dy = 0; dy < 3; dy++) {
            const int h2 = 2 * ho + dy - 1;
            if ((unsigned)h2 < (unsigned)Hn) {
                const float* xr = xc + (size_t)h2 * Wn;
                const int wb = 2 * px0 - 1;
                float xv[9];
                #pragma unroll
                for (int k = 0; k < 9; k++) {
                    const int wi = wb + k;
                    xv[k] = ((unsigned)wi < (unsigned)Wn) ? xr[wi] : 0.f;
                }
                #pragma unroll
                for (int p = 0; p < 4; p++)
                    #pragma unroll
                    for (int dx = 0; dx < 3; dx++)
                        o[p] = fmaf(lg[dy * 3 + dx][p], xv[2 * p + dx], o[p]);
            }
        }
        *(float4*)(out + ((size_t)(b * G_CI + ch) * HOo + ho) * WOo + px0) =
            make_float4(o[0], o[1], o[2], o[3]);
    }
}

// ---------------------------------------------------------------------------
// Kernel 4: cat conv 3x3 s2 p1 (12->24) + BN + leakyReLU, direct per-pixel.
// One thread = one output pixel, all 24 co. Weights in smem [ci][tap][co]
// so inner loop is LDS.128 broadcast (1 load per 4 FMA). No syncs in loop.
// ---------------------------------------------------------------------------
__global__ void __launch_bounds__(256)
conv_cat_direct(const float* __restrict__ x, const float* __restrict__ wgt,
                const float* __restrict__ bng, const float* __restrict__ bnb,
                const float* __restrict__ bnm, const float* __restrict__ bnv,
                float* __restrict__ y)
{
    using namespace cfg;
    __shared__ float ws[12 * 9 * 24];     // [ci][tap][co]
    __shared__ float sc_s[24], bi_s[24];

    const int tid = threadIdx.x;
    for (int i = tid; i < 2592; i += 256) {
        const int co = i % 24, tap = (i / 24) % 9, ci = i / 216;
        ws[i] = wgt[((size_t)co * 12 + ci) * 9 + tap];
    }
    if (tid < 24) {
        const float sc = bng[tid] * rsqrtf(bnv[tid] + 1e-5f);
        sc_s[tid] = sc;
        bi_s[tid] = bnb[tid] - bnm[tid] * sc;
    }
    __syncthreads();

    const int p  = blockIdx.x * 256 + tid;     // exactly B*HW threads
    const int b  = p / HW;
    const int q  = p - b * HW;
    const int ho = q / WOo, wo = q - ho * WOo;
    const float* xb = x + (size_t)b * 12 * HWin;

    float acc[24];
    #pragma unroll
    for (int co = 0; co < 24; co++) acc[co] = 0.f;

    for (int ci = 0; ci < 12; ci++) {
        const float* xc = xb + (size_t)ci * HWin;
        float xv[9];
        #pragma unroll
        for (int dy = 0; dy < 3; dy++) {
            const int h2 = 2 * ho - 1 + dy;
            const bool vr = (unsigned)h2 < (unsigned)Hn;
            const float* xr = xc + (size_t)h2 * Wn;
            #pragma unroll
            for (int dx = 0; dx < 3; dx++) {
                const int w2 = 2 * wo - 1 + dx;
                xv[dy * 3 + dx] = (vr && (unsigned)w2 < (unsigned)Wn) ? xr[w2] : 0.f;
            }
        }
        #pragma unroll
        for (int tap = 0; tap < 9; tap++) {
            const float xt = xv[tap];
            const float4* wv = (const float4*)&ws[(ci * 9 + tap) * 24];
            #pragma unroll
            for (int c4 = 0; c4 < 6; c4++) {
                const float4 w4 = wv[c4];
                acc[c4 * 4 + 0] = fmaf(xt, w4.x, acc[c4 * 4 + 0]);
                acc[c4 * 4 + 1] = fmaf(xt, w4.y, acc[c4 * 4 + 1]);
                acc[c4 * 4 + 2] = fmaf(xt, w4.z, acc[c4 * 4 + 2]);
                acc[c4 * 4 + 3] = fmaf(xt, w4.w, acc[c4 * 4 + 3]);
            }
        }
    }

    float* yb = y + (size_t)b * 24 * HW + q;
    #pragma unroll
    for (int co = 0; co < 24; co++) {
        float v = fmaf(acc[co], sc_s[co], bi_s[co]);
        v = (v >= 0.f) ? v : 0.1f * v;
        yb[(size_t)co * HW] = v;
    }
}

// ---------------------------------------------------------------------------
// Fused 1x1 conv -> softmax(9) -> unfold (cat path, CIY=24 — small, L1-served)
// ---------------------------------------------------------------------------
template<int CI_X, int CIY, int G, int CPG, int QUADS>
__global__ void __launch_bounds__(G * QUADS)
mask_softmax_unfold(const float* __restrict__ y, const float* __restrict__ w2,
                    const float* __restrict__ x, float* __restrict__ out)
{
    using namespace cfg;
    const int wo0 = blockIdx.x * (QUADS * 4);
    const int ho  = blockIdx.y;
    const int b   = blockIdx.z;
    const int tid = threadIdx.x;
    const int q   = tid % QUADS;
    const int g   = tid / QUADS;
    const int px0 = wo0 + q * 4;

    float lg[9][4];
    #pragma unroll
    for (int j = 0; j < 9; j++)
        #pragma unroll
        for (int p = 0; p < 4; p++) lg[j][p] = 0.f;

    const size_t ybase = (size_t)b * CIY * HW + (size_t)ho * WOo + px0;
    const float* wg = w2 + (size_t)g * 9 * CIY;

    for (int c4 = 0; c4 < CIY; c4 += 4) {
        float4 yv0 = *(const float4*)(y + ybase + (size_t)(c4 + 0) * HW);
        float4 yv1 = *(const float4*)(y + ybase + (size_t)(c4 + 1) * HW);
        float4 yv2 = *(const float4*)(y + ybase + (size_t)(c4 + 2) * HW);
        float4 yv3 = *(const float4*)(y + ybase + (size_t)(c4 + 3) * HW);
        #pragma unroll
        for (int j = 0; j < 9; j++) {
            float4 wv = *(const float4*)(wg + j * CIY + c4);
            lg[j][0] += wv.x * yv0.x + wv.y * yv1.x + wv.z * yv2.x + wv.w * yv3.x;
            lg[j][1] += wv.x * yv0.y + wv.y * yv1.y + wv.z * yv2.y + wv.w * yv3.y;
            lg[j][2] += wv.x * yv0.z + wv.y * yv1.z + wv.z * yv2.z + wv.w * yv3.z;
            lg[j][3] += wv.x * yv0.w + wv.y * yv1.w + wv.z * yv2.w + wv.w * yv3.w;
        }
    }

    #pragma unroll
    for (int p = 0; p < 4; p++) {
        float mx = lg[0][p];
        #pragma unroll
        for (int j = 1; j < 9; j++) mx = fmaxf(mx, lg[j][p]);
        float s = 0.f;
        #pragma unroll
        for (int j = 0; j < 9; j++) { float e = expf(lg[j][p] - mx); lg[j][p] = e; s += e; }
        const float inv = 1.f / s;
        #pragma unroll
        for (int j = 0; j < 9; j++) lg[j][p] *= inv;
    }

    #pragma unroll
    for (int io = 0; io < CPG; io++) {
        const int ch = io * G + g;
        const float* xc = x + (size_t)(b * CI_X + ch) * Hn * Wn;
        float o[4] = {0.f, 0.f, 0.f, 0.f};
        #pragma unroll
        for (int dy = 0; dy < 3; dy++) {
            const int h2 = 2 * ho + dy - 1;
            if ((unsigned)h2 < (unsigned)Hn) {
                const float* xr = xc + (size_t)h2 * Wn;
                const int wb = 2 * px0 - 1;
                float xv[9];
                #pragma unroll
                for (int k = 0; k < 9; k++) {
                    const int wi = wb + k;
                    xv[k] = ((unsigned)wi < (unsigned)Wn) ? xr[wi] : 0.f;
                }
                #pragma unroll
                for (int p = 0; p < 4; p++)
                    #pragma unroll
                    for (int dx = 0; dx < 3; dx++)
                        o[p] = fmaf(lg[dy * 3 + dx][p], xv[2 * p + dx], o[p]);
            }
        }
        *(float4*)(out + ((size_t)(b * CI_X + ch) * HOo + ho) * WOo + px0) =
            make_float4(o[0], o[1], o[2], o[3]);
    }
}

// ---------------------------------------------------------------------------
// Cost volumes
// ---------------------------------------------------------------------------
__global__ void __launch_bounds__(288)
gwc_volume_kernel(const float* __restrict__ g8x, float* __restrict__ out)
{
    using namespace cfg;
    __shared__ float rs[2][12][WOo];
    const int h  = blockIdx.x * 2 + threadIdx.y;
    const int g  = blockIdx.y;
    const int b  = blockIdx.z;
    const int w  = threadIdx.x;
    const int hy = threadIdx.y;

    const float* rbase = g8x + ((size_t)((b + 2) * G_CI + g * 12) * HOo + h) * WOo;
    #pragma unroll
    for (int c = 0; c < 12; c++)
        rs[hy][c][w] = rbase[(size_t)c * HW + w];
    __syncthreads();

    const float* lbase = g8x + ((size_t)(b * G_CI + g * 12) * HOo + h) * WOo + w;
    float lr[12];
    #pragma unroll
    for (int c = 0; c < 12; c++) lr[c] = lbase[(size_t)c * HW];

    for (int d = 0; d < Dd; d++) {
        float s = 0.f;
        if (w >= d) {
            #pragma unroll
            for (int c = 0; c < 12; c++) s = fmaf(lr[c], rs[hy][c][w - d], s);
            s *= (1.f / 12.f);
        }
        out[(((size_t)(b * 32 + g) * Dd + d) * HOo + h) * WOo + w] = s;
    }
}

__global__ void cat_volume_kernel(const float* __restrict__ c8x, float* __restrict__ out)
{
    using namespace cfg;
    const int idx = blockIdx.x * blockDim.x + threadIdx.x;
    constexpr int TOT = 2 * 24 * Dd * HW;
    if (idx >= TOT) return;
    int t = idx;
    const int w = t % WOo;  t /= WOo;
    const int h = t % HOo;  t /= HOo;
    const int d = t % Dd;   t /= Dd;
    const int cc = t % 24;
    const int b  = t / 24;

    float v = 0.f;
    if (w >= d) {
        if (cc < 12)
            v = c8x[((size_t)(b * 12 + cc) * HOo + h) * WOo + w];
        else
            v = c8x[((size_t)((b + 2) * 12 + (cc - 12)) * HOo + h) * WOo + (w - d)];
    }
    out[(((size_t)(b * 32 + 8 + cc) * Dd + d) * HOo + h) * WOo + w] = v;
}

// ---------------------------------------------------------------------------
// Launch
// ---------------------------------------------------------------------------
extern "C" void kernel_launch(void* const* d_in, const int* in_sizes, int n_in,
                              void* d_out, int out_size)
{
    const float* gx  = (const float*)d_in[0];
    const float* cx  = (const float*)d_in[1];
    const float* gw1 = (const float*)d_in[2];
    const float* gbg = (const float*)d_in[3];
    const float* gbb = (const float*)d_in[4];
    const float* gbm = (const float*)d_in[5];
    const float* gbv = (const float*)d_in[6];
    const float* gw2 = (const float*)d_in[7];
    const float* cw1 = (const float*)d_in[8];
    const float* cbg = (const float*)d_in[9];
    const float* cbb = (const float*)d_in[10];
    const float* cbm = (const float*)d_in[11];
    const float* cbv = (const float*)d_in[12];
    const float* cw2 = (const float*)d_in[13];
    float* out = (float*)d_out;

    float *y1, *g8x, *y2, *c8x, *msk;
    cudaGetSymbolAddress((void**)&y1,  d_y1);
    cudaGetSymbolAddress((void**)&g8x, d_g8x);
    cudaGetSymbolAddress((void**)&y2,  d_y2);
    cudaGetSymbolAddress((void**)&c8x, d_c8x);
    cudaGetSymbolAddress((void**)&msk, d_msk);

    cudaFuncSetAttribute(conv_gwc_mma, cudaFuncAttributeMaxDynamicSharedMemorySize, SM_CONV);
    cudaFuncSetAttribute(gemm_logits_mma, cudaFuncAttributeMaxDynamicSharedMemorySize, SM_LOG);

    wprep_kernel<<<(cfg::NCHUNK * 192 * 32 + 255) / 256, 256>>>(gw1);
    wprep2_kernel<<<(6 * 144 * 32 + 255) / 256, 256>>>(gw2);

    conv_gwc_mma<<<dim3(360, 2), 256, SM_CONV>>>(gx, gbg, gbb, gbm, gbv, y1);

    conv_cat_direct<<<(cfg::B * cfg::HW) / 256, 256>>>(
        cx, cw1, cbg, cbb, cbm, cbv, y2);

    gemm_logits_mma<<<360, 384, SM_LOG>>>(y1, msk);
    softmax_unfold_gwc<<<dim3(3, 80, 4), 192>>>(msk, gx, g8x);

    mask_softmax_unfold<12, 24, 12, 1, 12><<<dim3(3, 80, 4), 144>>>(y2, cw2, cx, c8x);

    gwc_volume_kernel<<<dim3(40, 8, 2), dim3(144, 2)>>>(g8x, out);
    cat_volume_kernel<<<(2 * 24 * cfg::Dd * cfg::HW + 255) / 256, 256>>>(c8x, out);
}